// round 6
// baseline (speedup 1.0000x reference)
#include <cuda_runtime.h>
#include <math.h>

#define B_    32
#define N_    577
#define DIM_  768
#define NH_   12
#define HD_   64
#define MLP_  3072
#define MTOK  (B_*N_)          /* 18464 */
#define QKVD  (3*DIM_)         /* 2304 */
#define SCALE_ 0.125f

// ---------------- scratch ----------------
__device__ float g_h   [(size_t)MTOK * DIM_];
__device__ float g_qkv [(size_t)MTOK * QKVD];
__device__ float g_att [(size_t)MTOK * DIM_];
__device__ float g_m   [(size_t)MTOK * MLP_];
__device__ float g_rpbf[(size_t)NH_ * N_ * N_];

// ---------------- helpers ----------------
__device__ __forceinline__ void cp16(void* dst, const void* src, bool valid) {
    unsigned d = (unsigned)__cvta_generic_to_shared(dst);
    int sz = valid ? 16 : 0;
    asm volatile("cp.async.cg.shared.global [%0], [%1], 16, %2;\n" :: "r"(d), "l"(src), "r"(sz));
}
__device__ __forceinline__ void cp_commit() { asm volatile("cp.async.commit_group;\n"); }
template<int Nw> __device__ __forceinline__ void cp_wait() {
    asm volatile("cp.async.wait_group %0;\n" :: "n"(Nw));
}
__device__ __forceinline__ void mma8(float* c, const unsigned* a, const unsigned* b) {
    asm volatile(
        "mma.sync.aligned.m16n8k8.row.col.f32.tf32.tf32.f32 "
        "{%0,%1,%2,%3},{%4,%5,%6,%7},{%8,%9},{%0,%1,%2,%3};"
        : "+f"(c[0]), "+f"(c[1]), "+f"(c[2]), "+f"(c[3])
        : "r"(a[0]), "r"(a[1]), "r"(a[2]), "r"(a[3]), "r"(b[0]), "r"(b[1]));
}

// ---------------- LayerNorm ----------------
__global__ void __launch_bounds__(256)
ln_kernel(const float* __restrict__ in, const float* __restrict__ g,
          const float* __restrict__ bta, float* __restrict__ out)
{
    __shared__ float red[16];
    __shared__ float s_stats[2];
    const int row = blockIdx.x;
    const int tid = threadIdx.x;
    const float* p = in + (size_t)row * DIM_;
    float v0 = p[tid], v1 = p[tid + 256], v2 = p[tid + 512];
    float s1 = v0 + v1 + v2;
    float s2 = v0*v0 + v1*v1 + v2*v2;
    #pragma unroll
    for (int o = 16; o > 0; o >>= 1) {
        s1 += __shfl_xor_sync(0xffffffffu, s1, o);
        s2 += __shfl_xor_sync(0xffffffffu, s2, o);
    }
    const int warp = tid >> 5, lane = tid & 31;
    if (lane == 0) { red[warp] = s1; red[warp + 8] = s2; }
    __syncthreads();
    if (tid == 0) {
        float t1 = 0.f, t2 = 0.f;
        #pragma unroll
        for (int w = 0; w < 8; w++) { t1 += red[w]; t2 += red[w + 8]; }
        float mean = t1 * (1.f / DIM_);
        float var  = t2 * (1.f / DIM_) - mean * mean;
        s_stats[0] = mean;
        s_stats[1] = rsqrtf(var + 1e-6f);
    }
    __syncthreads();
    const float mean = s_stats[0], inv = s_stats[1];
    float* o = out + (size_t)row * DIM_;
    o[tid]       = (v0 - mean) * inv * g[tid]       + bta[tid];
    o[tid + 256] = (v1 - mean) * inv * g[tid + 256] + bta[tid + 256];
    o[tid + 512] = (v2 - mean) * inv * g[tid + 512] + bta[tid + 512];
}

// ---------------- rel-pos bias expand ----------------
__global__ void rpb_expand(const float* __restrict__ table, const int* __restrict__ relidx,
                           float* __restrict__ out)
{
    int t = blockIdx.x * 256 + threadIdx.x;
    const int total = NH_ * N_ * N_;
    if (t >= total) return;
    int h = t / (N_ * N_);
    int r = t - h * (N_ * N_);
    out[t] = table[relidx[r] * NH_ + h];
}

// ---------------- TF32 tensor-core GEMM NT with cp.async 3-stage pipeline ----------------
// C[M,Nn] = A[M,K] @ Bw[Nn,K]^T + epilogue
// EPI 1: qkv concat bias   2: gelu(v+bias)   3: res + v + bias
#define GST 2560  /* floats per stage per matrix = 128*20 */
#define GEMM_SMEM (3 * GST * 2 * 4)

template<int EPI>
__global__ void __launch_bounds__(256, 2)
gemm_tc(const float* __restrict__ A, const float* __restrict__ Bw,
        float* __restrict__ C, int M, int Nn, int K,
        const float* __restrict__ bias, const float* __restrict__ bias2,
        const float* __restrict__ res)
{
    extern __shared__ float sm[];
    float* As = sm;             // [3][128*20]
    float* Bs = sm + 3 * GST;   // [3][128*20]

    const int tid = threadIdx.x;
    const int warp = tid >> 5, lane = tid & 31;
    const int groupID = lane >> 2, tid4 = lane & 3;
    const int warpM = warp & 1, warpN = warp >> 1;
    const int mBase = blockIdx.y * 128;
    const int nBase = blockIdx.x * 128;

    const int lr = tid >> 1;         // 0..127
    const int c0 = (tid & 1) * 8;    // 0 or 8

    const bool avok = (mBase + lr) < M;
    const float* Ap = A  + (size_t)(mBase + lr) * K + c0;
    const float* Bp = Bw + (size_t)(nBase + lr) * K + c0;

    float acc[4][4][4];
    #pragma unroll
    for (int i = 0; i < 4; i++)
        #pragma unroll
        for (int j = 0; j < 4; j++)
            #pragma unroll
            for (int r = 0; r < 4; r++) acc[i][j][r] = 0.f;

    const int nk = K >> 4;

    // issue loads for stage s covering k-slice ks*16
    auto issue = [&](int s, int ks) {
        float* ad = &As[s * GST + lr * 20 + c0];
        float* bd = &Bs[s * GST + lr * 20 + c0];
        const float* ap = Ap + ks * 16;
        const float* bp = Bp + ks * 16;
        cp16(ad,     avok ? ap     : A, avok);
        cp16(ad + 4, avok ? ap + 4 : A, avok);
        cp16(bd,     bp,     true);
        cp16(bd + 4, bp + 4, true);
    };

    issue(0, 0); cp_commit();
    issue(1, 1); cp_commit();

    for (int i = 0; i < nk; i++) {
        cp_wait<1>();
        __syncthreads();
        if (i + 2 < nk) issue((i + 2) % 3, i + 2);
        cp_commit();

        const unsigned* as = (const unsigned*)&As[(i % 3) * GST];
        const unsigned* bs = (const unsigned*)&Bs[(i % 3) * GST];
        #pragma unroll
        for (int kg = 0; kg < 16; kg += 8) {
            unsigned afr[4][4], bfr[4][2];
            #pragma unroll
            for (int ii = 0; ii < 4; ii++) {
                int r = warpM * 64 + ii * 16 + groupID;
                afr[ii][0] = as[r * 20 + kg + tid4];
                afr[ii][1] = as[(r + 8) * 20 + kg + tid4];
                afr[ii][2] = as[r * 20 + kg + tid4 + 4];
                afr[ii][3] = as[(r + 8) * 20 + kg + tid4 + 4];
            }
            #pragma unroll
            for (int j = 0; j < 4; j++) {
                int cn = warpN * 32 + j * 8 + groupID;
                bfr[j][0] = bs[cn * 20 + kg + tid4];
                bfr[j][1] = bs[cn * 20 + kg + tid4 + 4];
            }
            #pragma unroll
            for (int ii = 0; ii < 4; ii++)
                #pragma unroll
                for (int j = 0; j < 4; j++)
                    mma8(acc[ii][j], afr[ii], bfr[j]);
        }
        __syncthreads();
    }

    // epilogue
    #pragma unroll
    for (int i = 0; i < 4; i++) {
        int r0 = mBase + warpM * 64 + i * 16 + groupID;
        int r1 = r0 + 8;
        #pragma unroll
        for (int j = 0; j < 4; j++) {
            int cn = nBase + warpN * 32 + j * 8 + tid4 * 2;
            float bv0, bv1;
            if (EPI == 1) {
                bv0 = (cn < 768) ? bias[cn] : ((cn < 1536) ? 0.f : bias2[cn - 1536]);
                int c1 = cn + 1;
                bv1 = (c1 < 768) ? bias[c1] : ((c1 < 1536) ? 0.f : bias2[c1 - 1536]);
            } else {
                bv0 = bias[cn]; bv1 = bias[cn + 1];
            }
            #pragma unroll
            for (int rr = 0; rr < 2; rr++) {
                int gm = rr ? r1 : r0;
                if (gm >= M) continue;
                size_t off = (size_t)gm * Nn + cn;
                float v0 = acc[i][j][rr * 2 + 0] + bv0;
                float v1 = acc[i][j][rr * 2 + 1] + bv1;
                if (EPI == 2) {
                    v0 = 0.5f * v0 * (1.f + erff(v0 * 0.70710678118654752f));
                    v1 = 0.5f * v1 * (1.f + erff(v1 * 0.70710678118654752f));
                } else if (EPI == 3) {
                    v0 += res[off]; v1 += res[off + 1];
                }
                float2 o; o.x = v0; o.y = v1;
                *(float2*)&C[off] = o;
            }
        }
    }
}

// ---------------- flash attention: 128 queries/block, online softmax ----------------
#define KSTR 68
#define VSTR 72
#define PSTR 68
#define NCH  10     /* ceil(577/64) */
#define SKV_F (64*KSTR + 64*VSTR)                 /* floats per KV stage */
#define ATTN_SMEM ((2*SKV_F + 128*PSTR) * 4)      /* 106496 bytes */

__global__ void __launch_bounds__(256, 2)
attn_kernel(const float* __restrict__ qkv, const float* __restrict__ rpbf,
            float* __restrict__ out)
{
    extern __shared__ float sm[];
    float* sK0 = sm;                       // stage 0: K then V
    float* sV0 = sm + 64 * KSTR;
    float* sK1 = sm + SKV_F;               // stage 1
    float* sV1 = sK1 + 64 * KSTR;
    float* sP  = sm + 2 * SKV_F;           // 128*PSTR (also Q staging)

    const int tid = threadIdx.x;
    const int warp = tid >> 5, lane = tid & 31;
    const int groupID = lane >> 2, tid4 = lane & 3;
    const int q0 = blockIdx.x * 128;
    const int h  = blockIdx.y;
    const int b  = blockIdx.z;
    const size_t qkv_base = (size_t)b * N_ * QKVD + h * 64;

    // ---- Q load into sP via cp.async (8 float4 per thread) ----
    {
        const float* qsrc = qkv + qkv_base;
        #pragma unroll
        for (int p = 0; p < 8; p++) {
            int f4 = p * 256 + tid;          // 0..2047
            int row = f4 >> 4;               // 0..127
            int cc = (f4 & 15) * 4;
            int n = q0 + row;
            bool v = n < N_;
            cp16(&sP[row * PSTR + cc], v ? (qsrc + (size_t)n * QKVD + cc) : qkv, v);
        }
        cp_commit();
    }

    // ---- KV chunk loader ----
    auto issueKV = [&](int c) {
        float* kD = (c & 1) ? sK1 : sK0;
        float* vD = (c & 1) ? sV1 : sV0;
        const float* ks = qkv + qkv_base + 768;
        const float* vs = qkv + qkv_base + 1536;
        #pragma unroll
        for (int p = 0; p < 4; p++) {
            int f4 = p * 256 + tid;          // 0..1023
            int row = f4 >> 4;               // 0..63
            int cc = (f4 & 15) * 4;
            int kk = c * 64 + row;
            bool v = kk < N_;
            cp16(&kD[row * KSTR + cc], v ? (ks + (size_t)kk * QKVD + cc) : qkv, v);
            cp16(&vD[row * VSTR + cc], v ? (vs + (size_t)kk * QKVD + cc) : qkv, v);
        }
        cp_commit();
    };

    issueKV(0);
    issueKV(1);

    // ---- wait Q, read Q fragments into registers ----
    cp_wait<2>();
    __syncthreads();
    unsigned aq[8][4];
    {
        const unsigned* sPu = (const unsigned*)sP;
        int r = warp * 16 + groupID;
        #pragma unroll
        for (int kg = 0; kg < 8; kg++) {
            aq[kg][0] = sPu[r * PSTR + kg * 8 + tid4];
            aq[kg][1] = sPu[(r + 8) * PSTR + kg * 8 + tid4];
            aq[kg][2] = sPu[r * PSTR + kg * 8 + tid4 + 4];
            aq[kg][3] = sPu[(r + 8) * PSTR + kg * 8 + tid4 + 4];
        }
    }
    __syncthreads();   // everyone has Q frags; sP free for P

    const int n0 = q0 + warp * 16 + groupID;
    const int n1 = n0 + 8;
    const float* rpb0 = rpbf + ((size_t)h * N_ + (n0 < N_ ? n0 : 0)) * N_;
    const float* rpb1 = rpbf + ((size_t)h * N_ + (n1 < N_ ? n1 : 0)) * N_;

    float m0 = -1e30f, m1 = -1e30f, l0 = 0.f, l1 = 0.f;
    float oacc[8][4];
    #pragma unroll
    for (int j = 0; j < 8; j++)
        #pragma unroll
        for (int r = 0; r < 4; r++) oacc[j][r] = 0.f;

    for (int c = 0; c < NCH; c++) {
        cp_wait<1>();
        __syncthreads();
        const unsigned* sKu = (const unsigned*)((c & 1) ? sK1 : sK0);
        const unsigned* sVu = (const unsigned*)((c & 1) ? sV1 : sV0);

        // ---- S = Q K^T ----
        float sc[8][4];
        #pragma unroll
        for (int j = 0; j < 8; j++)
            #pragma unroll
            for (int r = 0; r < 4; r++) sc[j][r] = 0.f;
        #pragma unroll
        for (int kg = 0; kg < 8; kg++) {
            #pragma unroll
            for (int j = 0; j < 8; j++) {
                int kcol = j * 8 + groupID;
                unsigned bk[2];
                bk[0] = sKu[kcol * KSTR + kg * 8 + tid4];
                bk[1] = sKu[kcol * KSTR + kg * 8 + tid4 + 4];
                mma8(sc[j], aq[kg], bk);
            }
        }

        // ---- scale + rpb + mask; online softmax ----
        const int cbase = c * 64;
        float mx0 = m0, mx1 = m1;
        #pragma unroll
        for (int j = 0; j < 8; j++) {
            int col = cbase + j * 8 + tid4 * 2;
            bool v0 = col < N_, v1 = (col + 1) < N_;
            sc[j][0] = v0 ? sc[j][0] * SCALE_ + rpb0[col]     : -1e30f;
            sc[j][1] = v1 ? sc[j][1] * SCALE_ + rpb0[col + 1] : -1e30f;
            sc[j][2] = v0 ? sc[j][2] * SCALE_ + rpb1[col]     : -1e30f;
            sc[j][3] = v1 ? sc[j][3] * SCALE_ + rpb1[col + 1] : -1e30f;
            mx0 = fmaxf(mx0, fmaxf(sc[j][0], sc[j][1]));
            mx1 = fmaxf(mx1, fmaxf(sc[j][2], sc[j][3]));
        }
        #pragma unroll
        for (int o = 1; o <= 2; o <<= 1) {
            mx0 = fmaxf(mx0, __shfl_xor_sync(0xffffffffu, mx0, o));
            mx1 = fmaxf(mx1, __shfl_xor_sync(0xffffffffu, mx1, o));
        }
        float f0 = __expf(m0 - mx0), f1 = __expf(m1 - mx1);
        m0 = mx0; m1 = mx1;

        float rs0 = 0.f, rs1 = 0.f;
        {
            int rloc = warp * 16 + groupID;
            #pragma unroll
            for (int j = 0; j < 8; j++) {
                float p00 = __expf(sc[j][0] - m0);
                float p01 = __expf(sc[j][1] - m0);
                float p10 = __expf(sc[j][2] - m1);
                float p11 = __expf(sc[j][3] - m1);
                rs0 += p00 + p01; rs1 += p10 + p11;
                int col = j * 8 + tid4 * 2;
                float2 w0; w0.x = p00; w0.y = p01;
                float2 w1; w1.x = p10; w1.y = p11;
                *(float2*)&sP[rloc * PSTR + col] = w0;
                *(float2*)&sP[(rloc + 8) * PSTR + col] = w1;
            }
        }
        #pragma unroll
        for (int o = 1; o <= 2; o <<= 1) {
            rs0 += __shfl_xor_sync(0xffffffffu, rs0, o);
            rs1 += __shfl_xor_sync(0xffffffffu, rs1, o);
        }
        l0 = l0 * f0 + rs0;
        l1 = l1 * f1 + rs1;
        #pragma unroll
        for (int j = 0; j < 8; j++) {
            oacc[j][0] *= f0; oacc[j][1] *= f0;
            oacc[j][2] *= f1; oacc[j][3] *= f1;
        }
        __syncwarp();

        // ---- O += P V ----
        {
            const unsigned* sPu = (const unsigned*)sP;
            int rloc = warp * 16 + groupID;
            #pragma unroll
            for (int kg = 0; kg < 8; kg++) {
                unsigned ap[4];
                ap[0] = sPu[rloc * PSTR + kg * 8 + tid4];
                ap[1] = sPu[(rloc + 8) * PSTR + kg * 8 + tid4];
                ap[2] = sPu[rloc * PSTR + kg * 8 + tid4 + 4];
                ap[3] = sPu[(rloc + 8) * PSTR + kg * 8 + tid4 + 4];
                #pragma unroll
                for (int j = 0; j < 8; j++) {
                    int vcol = j * 8 + groupID;
                    unsigned bv[2];
                    bv[0] = sVu[(kg * 8 + tid4) * VSTR + vcol];
                    bv[1] = sVu[(kg * 8 + tid4 + 4) * VSTR + vcol];
                    mma8(oacc[j], ap, bv);
                }
            }
        }
        __syncthreads();
        if (c + 2 < NCH) issueKV(c + 2);
        else cp_commit();   // keep group accounting aligned
    }

    // ---- normalize + store ----
    {
        float inv0 = 1.f / l0, inv1 = 1.f / l1;
        #pragma unroll
        for (int j = 0; j < 8; j++) {
            int col = j * 8 + tid4 * 2;
            if (n0 < N_) {
                float2 o; o.x = oacc[j][0] * inv0; o.y = oacc[j][1] * inv0;
                *(float2*)&out[((size_t)b * N_ + n0) * DIM_ + h * 64 + col] = o;
            }
            if (n1 < N_) {
                float2 o; o.x = oacc[j][2] * inv1; o.y = oacc[j][3] * inv1;
                *(float2*)&out[((size_t)b * N_ + n1) * DIM_ + h * 64 + col] = o;
            }
        }
    }
}

// ---------------- launch ----------------
extern "C" void kernel_launch(void* const* d_in, const int* in_sizes, int n_in,
                              void* d_out, int out_size)
{
    const float* x     = (const float*)d_in[0];
    const float* n1g   = (const float*)d_in[1];
    const float* n1b   = (const float*)d_in[2];
    const float* qkvw  = (const float*)d_in[3];
    const float* qb    = (const float*)d_in[4];
    const float* vb    = (const float*)d_in[5];
    const float* rpbt  = (const float*)d_in[6];
    const float* projw = (const float*)d_in[7];
    const float* projb = (const float*)d_in[8];
    const float* n2g   = (const float*)d_in[9];
    const float* n2b   = (const float*)d_in[10];
    const float* fc1w  = (const float*)d_in[11];
    const float* fc1b  = (const float*)d_in[12];
    const float* fc2w  = (const float*)d_in[13];
    const float* fc2b  = (const float*)d_in[14];
    const int*   ridx  = (const int*)d_in[15];
    float* out = (float*)d_out;

    float *ph, *pqkv, *patt, *pm, *prpb;
    cudaGetSymbolAddress((void**)&ph,   g_h);
    cudaGetSymbolAddress((void**)&pqkv, g_qkv);
    cudaGetSymbolAddress((void**)&patt, g_att);
    cudaGetSymbolAddress((void**)&pm,   g_m);
    cudaGetSymbolAddress((void**)&prpb, g_rpbf);

    static bool attr_done = false;
    if (!attr_done) {
        cudaFuncSetAttribute(gemm_tc<1>, cudaFuncAttributeMaxDynamicSharedMemorySize, GEMM_SMEM);
        cudaFuncSetAttribute(gemm_tc<2>, cudaFuncAttributeMaxDynamicSharedMemorySize, GEMM_SMEM);
        cudaFuncSetAttribute(gemm_tc<3>, cudaFuncAttributeMaxDynamicSharedMemorySize, GEMM_SMEM);
        cudaFuncSetAttribute(attn_kernel, cudaFuncAttributeMaxDynamicSharedMemorySize, ATTN_SMEM);
        attr_done = true;
    }

    const int mTiles = (MTOK + 127) / 128;

    ln_kernel<<<MTOK, 256>>>(x, n1g, n1b, ph);
    rpb_expand<<<(NH_ * N_ * N_ + 255) / 256, 256>>>(rpbt, ridx, prpb);
    gemm_tc<1><<<dim3(QKVD / 128, mTiles), 256, GEMM_SMEM>>>(ph, qkvw, pqkv, MTOK, QKVD, DIM_, qb, vb, nullptr);
    attn_kernel<<<dim3((N_ + 127) / 128, NH_, B_), 256, ATTN_SMEM>>>(pqkv, prpb, patt);
    gemm_tc<3><<<dim3(DIM_ / 128, mTiles), 256, GEMM_SMEM>>>(patt, projw, out, MTOK, DIM_, DIM_, projb, nullptr, x);
    ln_kernel<<<MTOK, 256>>>(out, n2g, n2b, ph);
    gemm_tc<2><<<dim3(MLP_ / 128, mTiles), 256, GEMM_SMEM>>>(ph, fc1w, pm, MTOK, MLP_, DIM_, fc1b, nullptr, nullptr);
    gemm_tc<3><<<dim3(DIM_ / 128, mTiles), 256, GEMM_SMEM>>>(pm, fc2w, out, MTOK, DIM_, MLP_, fc2b, nullptr, out);
}

// round 7
// speedup vs baseline: 1.0011x; 1.0011x over previous
#include <cuda_runtime.h>
#include <math.h>

#define B_    32
#define N_    577
#define DIM_  768
#define NH_   12
#define HD_   64
#define MLP_  3072
#define MTOK  (B_*N_)          /* 18464 */
#define QKVD  (3*DIM_)         /* 2304 */
#define SCALE_ 0.125f

// ---------------- scratch ----------------
__device__ float g_h   [(size_t)MTOK * DIM_];
__device__ float g_qkv [(size_t)MTOK * QKVD];
__device__ float g_att [(size_t)MTOK * DIM_];
__device__ float g_m   [(size_t)MTOK * MLP_];
__device__ float g_rpbf[(size_t)NH_ * N_ * N_];

// ---------------- helpers ----------------
__device__ __forceinline__ void cp16(void* dst, const void* src, bool valid) {
    unsigned d = (unsigned)__cvta_generic_to_shared(dst);
    int sz = valid ? 16 : 0;
    asm volatile("cp.async.cg.shared.global [%0], [%1], 16, %2;\n" :: "r"(d), "l"(src), "r"(sz));
}
__device__ __forceinline__ void cp_commit() { asm volatile("cp.async.commit_group;\n"); }
template<int Nw> __device__ __forceinline__ void cp_wait() {
    asm volatile("cp.async.wait_group %0;\n" :: "n"(Nw));
}
__device__ __forceinline__ void mma8(float* c, const unsigned* a, const unsigned* b) {
    asm volatile(
        "mma.sync.aligned.m16n8k8.row.col.f32.tf32.tf32.f32 "
        "{%0,%1,%2,%3},{%4,%5,%6,%7},{%8,%9},{%0,%1,%2,%3};"
        : "+f"(c[0]), "+f"(c[1]), "+f"(c[2]), "+f"(c[3])
        : "r"(a[0]), "r"(a[1]), "r"(a[2]), "r"(a[3]), "r"(b[0]), "r"(b[1]));
}

// ---------------- LayerNorm ----------------
__global__ void __launch_bounds__(256)
ln_kernel(const float* __restrict__ in, const float* __restrict__ g,
          const float* __restrict__ bta, float* __restrict__ out)
{
    __shared__ float red[16];
    __shared__ float s_stats[2];
    const int row = blockIdx.x;
    const int tid = threadIdx.x;
    const float* p = in + (size_t)row * DIM_;
    float v0 = p[tid], v1 = p[tid + 256], v2 = p[tid + 512];
    float s1 = v0 + v1 + v2;
    float s2 = v0*v0 + v1*v1 + v2*v2;
    #pragma unroll
    for (int o = 16; o > 0; o >>= 1) {
        s1 += __shfl_xor_sync(0xffffffffu, s1, o);
        s2 += __shfl_xor_sync(0xffffffffu, s2, o);
    }
    const int warp = tid >> 5, lane = tid & 31;
    if (lane == 0) { red[warp] = s1; red[warp + 8] = s2; }
    __syncthreads();
    if (tid == 0) {
        float t1 = 0.f, t2 = 0.f;
        #pragma unroll
        for (int w = 0; w < 8; w++) { t1 += red[w]; t2 += red[w + 8]; }
        float mean = t1 * (1.f / DIM_);
        float var  = t2 * (1.f / DIM_) - mean * mean;
        s_stats[0] = mean;
        s_stats[1] = rsqrtf(var + 1e-6f);
    }
    __syncthreads();
    const float mean = s_stats[0], inv = s_stats[1];
    float* o = out + (size_t)row * DIM_;
    o[tid]       = (v0 - mean) * inv * g[tid]       + bta[tid];
    o[tid + 256] = (v1 - mean) * inv * g[tid + 256] + bta[tid + 256];
    o[tid + 512] = (v2 - mean) * inv * g[tid + 512] + bta[tid + 512];
}

// ---------------- rel-pos bias expand ----------------
__global__ void rpb_expand(const float* __restrict__ table, const int* __restrict__ relidx,
                           float* __restrict__ out)
{
    int t = blockIdx.x * 256 + threadIdx.x;
    const int total = NH_ * N_ * N_;
    if (t >= total) return;
    int h = t / (N_ * N_);
    int r = t - h * (N_ * N_);
    out[t] = table[relidx[r] * NH_ + h];
}

// ---------------- TF32 tensor-core GEMM NT, 4-stage cp.async, 1 barrier/iter ----------------
// C[M,Nn] = A[M,K] @ Bw[Nn,K]^T + epilogue
// EPI 1: qkv concat bias   2: gelu(v+bias)   3: res + v + bias
#define GSTAGES 4
#define GST 2560  /* floats per stage per matrix = 128*20 */
#define GEMM_SMEM (GSTAGES * GST * 2 * 4)

template<int EPI>
__global__ void __launch_bounds__(256, 2)
gemm_tc(const float* __restrict__ A, const float* __restrict__ Bw,
        float* __restrict__ C, int M, int Nn, int K,
        const float* __restrict__ bias, const float* __restrict__ bias2,
        const float* __restrict__ res)
{
    extern __shared__ float sm[];
    float* As = sm;                   // [GSTAGES][128*20]
    float* Bs = sm + GSTAGES * GST;   // [GSTAGES][128*20]

    const int tid = threadIdx.x;
    const int warp = tid >> 5, lane = tid & 31;
    const int groupID = lane >> 2, tid4 = lane & 3;
    const int warpM = warp & 1, warpN = warp >> 1;
    const int mBase = blockIdx.y * 128;
    const int nBase = blockIdx.x * 128;

    const int lr = tid >> 1;         // 0..127
    const int c0 = (tid & 1) * 8;    // 0 or 8

    const bool avok = (mBase + lr) < M;
    const float* Ap = A  + (size_t)(mBase + lr) * K + c0;
    const float* Bp = Bw + (size_t)(nBase + lr) * K + c0;

    float acc[4][4][4];
    #pragma unroll
    for (int i = 0; i < 4; i++)
        #pragma unroll
        for (int j = 0; j < 4; j++)
            #pragma unroll
            for (int r = 0; r < 4; r++) acc[i][j][r] = 0.f;

    const int nk = K >> 4;

    auto issue = [&](int s, int ks) {
        float* ad = &As[s * GST + lr * 20 + c0];
        float* bd = &Bs[s * GST + lr * 20 + c0];
        const float* ap = Ap + ks * 16;
        const float* bp = Bp + ks * 16;
        cp16(ad,     avok ? ap     : A, avok);
        cp16(ad + 4, avok ? ap + 4 : A, avok);
        cp16(bd,     bp,     true);
        cp16(bd + 4, bp + 4, true);
    };

    issue(0, 0); cp_commit();
    issue(1, 1); cp_commit();
    issue(2, 2); cp_commit();

    for (int i = 0; i < nk; i++) {
        cp_wait<2>();
        __syncthreads();
        if (i + 3 < nk) issue((i + 3) & 3, i + 3);
        cp_commit();

        const unsigned* as = (const unsigned*)&As[(i & 3) * GST];
        const unsigned* bs = (const unsigned*)&Bs[(i & 3) * GST];

        unsigned afr[2][4][4], bfr[2][4][2];
        // prefetch kg=0 fragments
        #pragma unroll
        for (int ii = 0; ii < 4; ii++) {
            int r = warpM * 64 + ii * 16 + groupID;
            afr[0][ii][0] = as[r * 20 + tid4];
            afr[0][ii][1] = as[(r + 8) * 20 + tid4];
            afr[0][ii][2] = as[r * 20 + tid4 + 4];
            afr[0][ii][3] = as[(r + 8) * 20 + tid4 + 4];
        }
        #pragma unroll
        for (int j = 0; j < 4; j++) {
            int cn = warpN * 32 + j * 8 + groupID;
            bfr[0][j][0] = bs[cn * 20 + tid4];
            bfr[0][j][1] = bs[cn * 20 + tid4 + 4];
        }
        #pragma unroll
        for (int kh = 0; kh < 2; kh++) {
            if (kh == 0) {
                // prefetch kg=8 fragments while kg=0 MMAs issue below
                #pragma unroll
                for (int ii = 0; ii < 4; ii++) {
                    int r = warpM * 64 + ii * 16 + groupID;
                    afr[1][ii][0] = as[r * 20 + 8 + tid4];
                    afr[1][ii][1] = as[(r + 8) * 20 + 8 + tid4];
                    afr[1][ii][2] = as[r * 20 + 8 + tid4 + 4];
                    afr[1][ii][3] = as[(r + 8) * 20 + 8 + tid4 + 4];
                }
                #pragma unroll
                for (int j = 0; j < 4; j++) {
                    int cn = warpN * 32 + j * 8 + groupID;
                    bfr[1][j][0] = bs[cn * 20 + 8 + tid4];
                    bfr[1][j][1] = bs[cn * 20 + 8 + tid4 + 4];
                }
            }
            #pragma unroll
            for (int ii = 0; ii < 4; ii++)
                #pragma unroll
                for (int j = 0; j < 4; j++)
                    mma8(acc[ii][j], afr[kh][ii], bfr[kh][j]);
        }
        // no bottom barrier: next iteration's top barrier orders reads
        // of stage i%4 before any cp.async writes into it.
    }

    // epilogue
    #pragma unroll
    for (int i = 0; i < 4; i++) {
        int r0 = mBase + warpM * 64 + i * 16 + groupID;
        int r1 = r0 + 8;
        #pragma unroll
        for (int j = 0; j < 4; j++) {
            int cn = nBase + warpN * 32 + j * 8 + tid4 * 2;
            float bv0, bv1;
            if (EPI == 1) {
                bv0 = (cn < 768) ? bias[cn] : ((cn < 1536) ? 0.f : bias2[cn - 1536]);
                int c1 = cn + 1;
                bv1 = (c1 < 768) ? bias[c1] : ((c1 < 1536) ? 0.f : bias2[c1 - 1536]);
            } else {
                bv0 = bias[cn]; bv1 = bias[cn + 1];
            }
            #pragma unroll
            for (int rr = 0; rr < 2; rr++) {
                int gm = rr ? r1 : r0;
                if (gm >= M) continue;
                size_t off = (size_t)gm * Nn + cn;
                float v0 = acc[i][j][rr * 2 + 0] + bv0;
                float v1 = acc[i][j][rr * 2 + 1] + bv1;
                if (EPI == 2) {
                    v0 = 0.5f * v0 * (1.f + erff(v0 * 0.70710678118654752f));
                    v1 = 0.5f * v1 * (1.f + erff(v1 * 0.70710678118654752f));
                } else if (EPI == 3) {
                    v0 += res[off]; v1 += res[off + 1];
                }
                float2 o; o.x = v0; o.y = v1;
                *(float2*)&C[off] = o;
            }
        }
    }
}

// ---------------- flash attention: 128 queries/block, online softmax ----------------
#define KSTR 68
#define VSTR 72
#define PSTR 68
#define NCH  10     /* ceil(577/64) */
#define SKV_F (64*KSTR + 64*VSTR)                 /* floats per KV stage */
#define ATTN_SMEM ((2*SKV_F + 128*PSTR) * 4)      /* 106496 bytes */

__global__ void __launch_bounds__(256, 2)
attn_kernel(const float* __restrict__ qkv, const float* __restrict__ rpbf,
            float* __restrict__ out)
{
    extern __shared__ float sm[];
    float* sK0 = sm;
    float* sV0 = sm + 64 * KSTR;
    float* sK1 = sm + SKV_F;
    float* sV1 = sK1 + 64 * KSTR;
    float* sP  = sm + 2 * SKV_F;

    const int tid = threadIdx.x;
    const int warp = tid >> 5, lane = tid & 31;
    const int groupID = lane >> 2, tid4 = lane & 3;
    const int q0 = blockIdx.x * 128;
    const int h  = blockIdx.y;
    const int b  = blockIdx.z;
    const size_t qkv_base = (size_t)b * N_ * QKVD + h * 64;

    {
        const float* qsrc = qkv + qkv_base;
        #pragma unroll
        for (int p = 0; p < 8; p++) {
            int f4 = p * 256 + tid;
            int row = f4 >> 4;
            int cc = (f4 & 15) * 4;
            int n = q0 + row;
            bool v = n < N_;
            cp16(&sP[row * PSTR + cc], v ? (qsrc + (size_t)n * QKVD + cc) : qkv, v);
        }
        cp_commit();
    }

    auto issueKV = [&](int c) {
        float* kD = (c & 1) ? sK1 : sK0;
        float* vD = (c & 1) ? sV1 : sV0;
        const float* ks = qkv + qkv_base + 768;
        const float* vs = qkv + qkv_base + 1536;
        #pragma unroll
        for (int p = 0; p < 4; p++) {
            int f4 = p * 256 + tid;
            int row = f4 >> 4;
            int cc = (f4 & 15) * 4;
            int kk = c * 64 + row;
            bool v = kk < N_;
            cp16(&kD[row * KSTR + cc], v ? (ks + (size_t)kk * QKVD + cc) : qkv, v);
            cp16(&vD[row * VSTR + cc], v ? (vs + (size_t)kk * QKVD + cc) : qkv, v);
        }
        cp_commit();
    };

    issueKV(0);
    issueKV(1);

    cp_wait<2>();
    __syncthreads();
    unsigned aq[8][4];
    {
        const unsigned* sPu = (const unsigned*)sP;
        int r = warp * 16 + groupID;
        #pragma unroll
        for (int kg = 0; kg < 8; kg++) {
            aq[kg][0] = sPu[r * PSTR + kg * 8 + tid4];
            aq[kg][1] = sPu[(r + 8) * PSTR + kg * 8 + tid4];
            aq[kg][2] = sPu[r * PSTR + kg * 8 + tid4 + 4];
            aq[kg][3] = sPu[(r + 8) * PSTR + kg * 8 + tid4 + 4];
        }
    }
    __syncthreads();

    const int n0 = q0 + warp * 16 + groupID;
    const int n1 = n0 + 8;
    const float* rpb0 = rpbf + ((size_t)h * N_ + (n0 < N_ ? n0 : 0)) * N_;
    const float* rpb1 = rpbf + ((size_t)h * N_ + (n1 < N_ ? n1 : 0)) * N_;

    float m0 = -1e30f, m1 = -1e30f, l0 = 0.f, l1 = 0.f;
    float oacc[8][4];
    #pragma unroll
    for (int j = 0; j < 8; j++)
        #pragma unroll
        for (int r = 0; r < 4; r++) oacc[j][r] = 0.f;

    for (int c = 0; c < NCH; c++) {
        cp_wait<1>();
        __syncthreads();
        const unsigned* sKu = (const unsigned*)((c & 1) ? sK1 : sK0);
        const unsigned* sVu = (const unsigned*)((c & 1) ? sV1 : sV0);

        float sc[8][4];
        #pragma unroll
        for (int j = 0; j < 8; j++)
            #pragma unroll
            for (int r = 0; r < 4; r++) sc[j][r] = 0.f;
        #pragma unroll
        for (int kg = 0; kg < 8; kg++) {
            #pragma unroll
            for (int j = 0; j < 8; j++) {
                int kcol = j * 8 + groupID;
                unsigned bk[2];
                bk[0] = sKu[kcol * KSTR + kg * 8 + tid4];
                bk[1] = sKu[kcol * KSTR + kg * 8 + tid4 + 4];
                mma8(sc[j], aq[kg], bk);
            }
        }

        const int cbase = c * 64;
        float mx0 = m0, mx1 = m1;
        #pragma unroll
        for (int j = 0; j < 8; j++) {
            int col = cbase + j * 8 + tid4 * 2;
            bool v0 = col < N_, v1 = (col + 1) < N_;
            sc[j][0] = v0 ? sc[j][0] * SCALE_ + rpb0[col]     : -1e30f;
            sc[j][1] = v1 ? sc[j][1] * SCALE_ + rpb0[col + 1] : -1e30f;
            sc[j][2] = v0 ? sc[j][2] * SCALE_ + rpb1[col]     : -1e30f;
            sc[j][3] = v1 ? sc[j][3] * SCALE_ + rpb1[col + 1] : -1e30f;
            mx0 = fmaxf(mx0, fmaxf(sc[j][0], sc[j][1]));
            mx1 = fmaxf(mx1, fmaxf(sc[j][2], sc[j][3]));
        }
        #pragma unroll
        for (int o = 1; o <= 2; o <<= 1) {
            mx0 = fmaxf(mx0, __shfl_xor_sync(0xffffffffu, mx0, o));
            mx1 = fmaxf(mx1, __shfl_xor_sync(0xffffffffu, mx1, o));
        }
        float f0 = __expf(m0 - mx0), f1 = __expf(m1 - mx1);
        m0 = mx0; m1 = mx1;

        float rs0 = 0.f, rs1 = 0.f;
        {
            int rloc = warp * 16 + groupID;
            #pragma unroll
            for (int j = 0; j < 8; j++) {
                float p00 = __expf(sc[j][0] - m0);
                float p01 = __expf(sc[j][1] - m0);
                float p10 = __expf(sc[j][2] - m1);
                float p11 = __expf(sc[j][3] - m1);
                rs0 += p00 + p01; rs1 += p10 + p11;
                int col = j * 8 + tid4 * 2;
                float2 w0; w0.x = p00; w0.y = p01;
                float2 w1; w1.x = p10; w1.y = p11;
                *(float2*)&sP[rloc * PSTR + col] = w0;
                *(float2*)&sP[(rloc + 8) * PSTR + col] = w1;
            }
        }
        #pragma unroll
        for (int o = 1; o <= 2; o <<= 1) {
            rs0 += __shfl_xor_sync(0xffffffffu, rs0, o);
            rs1 += __shfl_xor_sync(0xffffffffu, rs1, o);
        }
        l0 = l0 * f0 + rs0;
        l1 = l1 * f1 + rs1;
        #pragma unroll
        for (int j = 0; j < 8; j++) {
            oacc[j][0] *= f0; oacc[j][1] *= f0;
            oacc[j][2] *= f1; oacc[j][3] *= f1;
        }
        __syncwarp();

        {
            const unsigned* sPu = (const unsigned*)sP;
            int rloc = warp * 16 + groupID;
            #pragma unroll
            for (int kg = 0; kg < 8; kg++) {
                unsigned ap[4];
                ap[0] = sPu[rloc * PSTR + kg * 8 + tid4];
                ap[1] = sPu[(rloc + 8) * PSTR + kg * 8 + tid4];
                ap[2] = sPu[rloc * PSTR + kg * 8 + tid4 + 4];
                ap[3] = sPu[(rloc + 8) * PSTR + kg * 8 + tid4 + 4];
                #pragma unroll
                for (int j = 0; j < 8; j++) {
                    int vcol = j * 8 + groupID;
                    unsigned bv[2];
                    bv[0] = sVu[(kg * 8 + tid4) * VSTR + vcol];
                    bv[1] = sVu[(kg * 8 + tid4 + 4) * VSTR + vcol];
                    mma8(oacc[j], ap, bv);
                }
            }
        }
        __syncthreads();
        if (c + 2 < NCH) issueKV(c + 2);
        else cp_commit();
    }

    {
        float inv0 = 1.f / l0, inv1 = 1.f / l1;
        #pragma unroll
        for (int j = 0; j < 8; j++) {
            int col = j * 8 + tid4 * 2;
            if (n0 < N_) {
                float2 o; o.x = oacc[j][0] * inv0; o.y = oacc[j][1] * inv0;
                *(float2*)&out[((size_t)b * N_ + n0) * DIM_ + h * 64 + col] = o;
            }
            if (n1 < N_) {
                float2 o; o.x = oacc[j][2] * inv1; o.y = oacc[j][3] * inv1;
                *(float2*)&out[((size_t)b * N_ + n1) * DIM_ + h * 64 + col] = o;
            }
        }
    }
}

// ---------------- launch ----------------
extern "C" void kernel_launch(void* const* d_in, const int* in_sizes, int n_in,
                              void* d_out, int out_size)
{
    const float* x     = (const float*)d_in[0];
    const float* n1g   = (const float*)d_in[1];
    const float* n1b   = (const float*)d_in[2];
    const float* qkvw  = (const float*)d_in[3];
    const float* qb    = (const float*)d_in[4];
    const float* vb    = (const float*)d_in[5];
    const float* rpbt  = (const float*)d_in[6];
    const float* projw = (const float*)d_in[7];
    const float* projb = (const float*)d_in[8];
    const float* n2g   = (const float*)d_in[9];
    const float* n2b   = (const float*)d_in[10];
    const float* fc1w  = (const float*)d_in[11];
    const float* fc1b  = (const float*)d_in[12];
    const float* fc2w  = (const float*)d_in[13];
    const float* fc2b  = (const float*)d_in[14];
    const int*   ridx  = (const int*)d_in[15];
    float* out = (float*)d_out;

    float *ph, *pqkv, *patt, *pm, *prpb;
    cudaGetSymbolAddress((void**)&ph,   g_h);
    cudaGetSymbolAddress((void**)&pqkv, g_qkv);
    cudaGetSymbolAddress((void**)&patt, g_att);
    cudaGetSymbolAddress((void**)&pm,   g_m);
    cudaGetSymbolAddress((void**)&prpb, g_rpbf);

    static bool attr_done = false;
    if (!attr_done) {
        cudaFuncSetAttribute(gemm_tc<1>, cudaFuncAttributeMaxDynamicSharedMemorySize, GEMM_SMEM);
        cudaFuncSetAttribute(gemm_tc<2>, cudaFuncAttributeMaxDynamicSharedMemorySize, GEMM_SMEM);
        cudaFuncSetAttribute(gemm_tc<3>, cudaFuncAttributeMaxDynamicSharedMemorySize, GEMM_SMEM);
        cudaFuncSetAttribute(attn_kernel, cudaFuncAttributeMaxDynamicSharedMemorySize, ATTN_SMEM);
        attr_done = true;
    }

    const int mTiles = (MTOK + 127) / 128;

    ln_kernel<<<MTOK, 256>>>(x, n1g, n1b, ph);
    rpb_expand<<<(NH_ * N_ * N_ + 255) / 256, 256>>>(rpbt, ridx, prpb);
    gemm_tc<1><<<dim3(QKVD / 128, mTiles), 256, GEMM_SMEM>>>(ph, qkvw, pqkv, MTOK, QKVD, DIM_, qb, vb, nullptr);
    attn_kernel<<<dim3((N_ + 127) / 128, NH_, B_), 256, ATTN_SMEM>>>(pqkv, prpb, patt);
    gemm_tc<3><<<dim3(DIM_ / 128, mTiles), 256, GEMM_SMEM>>>(patt, projw, out, MTOK, DIM_, DIM_, projb, nullptr, x);
    ln_kernel<<<MTOK, 256>>>(out, n2g, n2b, ph);
    gemm_tc<2><<<dim3(MLP_ / 128, mTiles), 256, GEMM_SMEM>>>(ph, fc1w, pm, MTOK, MLP_, DIM_, fc1b, nullptr, nullptr);
    gemm_tc<3><<<dim3(DIM_ / 128, mTiles), 256, GEMM_SMEM>>>(pm, fc2w, out, MTOK, DIM_, MLP_, fc2b, nullptr, out);
}

// round 8
// speedup vs baseline: 1.6162x; 1.6144x over previous
#include <cuda_runtime.h>
#include <cuda_fp16.h>
#include <math.h>

#define B_    32
#define N_    577
#define DIM_  768
#define NH_   12
#define HD_   64
#define MLP_  3072
#define MTOK  (B_*N_)          /* 18464 */
#define QKVD  (3*DIM_)         /* 2304 */
#define SCALE_ 0.125f

// ---------------- scratch ----------------
__device__ __align__(16) __half g_h   [(size_t)MTOK * DIM_];    // LN out (fp16)
__device__ __align__(16) float  g_qkv [(size_t)MTOK * QKVD];    // qkv (fp32, for attn)
__device__ __align__(16) __half g_att [(size_t)MTOK * DIM_];    // attn out (fp16)
__device__ __align__(16) __half g_m   [(size_t)MTOK * MLP_];    // MLP hidden (fp16)
__device__ __align__(16) float  g_rpbf[(size_t)NH_ * N_ * N_];
// fp16 weight copies
__device__ __align__(16) __half g_wqkv[(size_t)QKVD * DIM_];
__device__ __align__(16) __half g_wproj[(size_t)DIM_ * DIM_];
__device__ __align__(16) __half g_wfc1[(size_t)MLP_ * DIM_];
__device__ __align__(16) __half g_wfc2[(size_t)DIM_ * MLP_];

// ---------------- helpers ----------------
__device__ __forceinline__ void cp16(void* dst, const void* src, bool valid) {
    unsigned d = (unsigned)__cvta_generic_to_shared(dst);
    int sz = valid ? 16 : 0;
    asm volatile("cp.async.cg.shared.global [%0], [%1], 16, %2;\n" :: "r"(d), "l"(src), "r"(sz));
}
__device__ __forceinline__ void cp_commit() { asm volatile("cp.async.commit_group;\n"); }
template<int Nw> __device__ __forceinline__ void cp_wait() {
    asm volatile("cp.async.wait_group %0;\n" :: "n"(Nw));
}
// tf32 mma (attention)
__device__ __forceinline__ void mma8(float* c, const unsigned* a, const unsigned* b) {
    asm volatile(
        "mma.sync.aligned.m16n8k8.row.col.f32.tf32.tf32.f32 "
        "{%0,%1,%2,%3},{%4,%5,%6,%7},{%8,%9},{%0,%1,%2,%3};"
        : "+f"(c[0]), "+f"(c[1]), "+f"(c[2]), "+f"(c[3])
        : "r"(a[0]), "r"(a[1]), "r"(a[2]), "r"(a[3]), "r"(b[0]), "r"(b[1]));
}
// fp16 mma (GEMMs)
__device__ __forceinline__ void mma16(float* c, const unsigned* a, const unsigned* b) {
    asm volatile(
        "mma.sync.aligned.m16n8k16.row.col.f32.f16.f16.f32 "
        "{%0,%1,%2,%3},{%4,%5,%6,%7},{%8,%9},{%0,%1,%2,%3};"
        : "+f"(c[0]), "+f"(c[1]), "+f"(c[2]), "+f"(c[3])
        : "r"(a[0]), "r"(a[1]), "r"(a[2]), "r"(a[3]), "r"(b[0]), "r"(b[1]));
}

// ---------------- fp32 -> fp16 weight convert ----------------
__global__ void f2h_kernel(const float* __restrict__ s, __half* __restrict__ d, int n4)
{
    int i = blockIdx.x * 256 + threadIdx.x;
    if (i >= n4) return;
    float4 v = *(const float4*)(s + (size_t)i * 4);
    __half2 lo = __floats2half2_rn(v.x, v.y);
    __half2 hi = __floats2half2_rn(v.z, v.w);
    *(__half2*)(d + (size_t)i * 4)     = lo;
    *(__half2*)(d + (size_t)i * 4 + 2) = hi;
}

// ---------------- LayerNorm (fp32 in -> fp16 out) ----------------
__global__ void __launch_bounds__(256)
ln_kernel(const float* __restrict__ in, const float* __restrict__ g,
          const float* __restrict__ bta, __half* __restrict__ out)
{
    __shared__ float red[16];
    __shared__ float s_stats[2];
    const int row = blockIdx.x;
    const int tid = threadIdx.x;
    const float* p = in + (size_t)row * DIM_;
    float v0 = p[tid], v1 = p[tid + 256], v2 = p[tid + 512];
    float s1 = v0 + v1 + v2;
    float s2 = v0*v0 + v1*v1 + v2*v2;
    #pragma unroll
    for (int o = 16; o > 0; o >>= 1) {
        s1 += __shfl_xor_sync(0xffffffffu, s1, o);
        s2 += __shfl_xor_sync(0xffffffffu, s2, o);
    }
    const int warp = tid >> 5, lane = tid & 31;
    if (lane == 0) { red[warp] = s1; red[warp + 8] = s2; }
    __syncthreads();
    if (tid == 0) {
        float t1 = 0.f, t2 = 0.f;
        #pragma unroll
        for (int w = 0; w < 8; w++) { t1 += red[w]; t2 += red[w + 8]; }
        float mean = t1 * (1.f / DIM_);
        float var  = t2 * (1.f / DIM_) - mean * mean;
        s_stats[0] = mean;
        s_stats[1] = rsqrtf(var + 1e-6f);
    }
    __syncthreads();
    const float mean = s_stats[0], inv = s_stats[1];
    __half* o = out + (size_t)row * DIM_;
    o[tid]       = __float2half_rn((v0 - mean) * inv * g[tid]       + bta[tid]);
    o[tid + 256] = __float2half_rn((v1 - mean) * inv * g[tid + 256] + bta[tid + 256]);
    o[tid + 512] = __float2half_rn((v2 - mean) * inv * g[tid + 512] + bta[tid + 512]);
}

// ---------------- rel-pos bias expand ----------------
__global__ void rpb_expand(const float* __restrict__ table, const int* __restrict__ relidx,
                           float* __restrict__ out)
{
    int t = blockIdx.x * 256 + threadIdx.x;
    const int total = NH_ * N_ * N_;
    if (t >= total) return;
    int h = t / (N_ * N_);
    int r = t - h * (N_ * N_);
    out[t] = table[relidx[r] * NH_ + h];
}

// ---------------- FP16 tensor-core GEMM NT, 4-stage cp.async ----------------
// C[M,Nn] = A[M,K] @ Bw[Nn,K]^T + epilogue
// EPI 1: qkv concat bias -> fp32 out
// EPI 2: gelu(v+bias)    -> fp16 out
// EPI 3: res + v + bias  -> fp32 out
#define GSTAGES 4
#define GSTRIDE 20                       /* u32 per row (32 halves data + 8 pad) */
#define GST_U32 (128 * GSTRIDE)          /* 2560 u32 per stage per matrix */
#define GEMM_SMEM (GSTAGES * GST_U32 * 2 * 4)   /* 81920 B */

template<int EPI>
__global__ void __launch_bounds__(256, 2)
gemm_h(const __half* __restrict__ A, const __half* __restrict__ Bw,
       void* __restrict__ Cv, int M, int Nn, int K,
       const float* __restrict__ bias, const float* __restrict__ bias2,
       const float* __restrict__ res)
{
    extern __shared__ unsigned smu[];
    unsigned* As = smu;                      // [GSTAGES][2560]
    unsigned* Bs = smu + GSTAGES * GST_U32;  // [GSTAGES][2560]

    const int tid = threadIdx.x;
    const int warp = tid >> 5, lane = tid & 31;
    const int groupID = lane >> 2, tid4 = lane & 3;
    const int warpM = warp & 1, warpN = warp >> 1;
    const int mBase = blockIdx.y * 128;
    const int nBase = blockIdx.x * 128;

    const int lr  = tid >> 1;          // 0..127
    const int c0h = (tid & 1) * 16;    // half offset: 0 or 16

    const bool avok = (mBase + lr) < M;
    const __half* Ap = A  + (size_t)(mBase + lr) * K + c0h;
    const __half* Bp = Bw + (size_t)(nBase + lr) * K + c0h;

    float acc[4][4][4];
    #pragma unroll
    for (int i = 0; i < 4; i++)
        #pragma unroll
        for (int j = 0; j < 4; j++)
            #pragma unroll
            for (int r = 0; r < 4; r++) acc[i][j][r] = 0.f;

    const int nk = K >> 5;   // k-tile = 32

    auto issue = [&](int s, int ks) {
        unsigned* ad = &As[s * GST_U32 + lr * GSTRIDE + (c0h >> 1)];
        unsigned* bd = &Bs[s * GST_U32 + lr * GSTRIDE + (c0h >> 1)];
        const __half* ap = Ap + ks * 32;
        const __half* bp = Bp + ks * 32;
        cp16(ad,     avok ? ap     : (const __half*)A, avok);
        cp16(ad + 4, avok ? ap + 8 : (const __half*)A, avok);
        cp16(bd,     bp,     true);
        cp16(bd + 4, bp + 8, true);
    };

    issue(0, 0); cp_commit();
    issue(1, 1); cp_commit();
    issue(2, 2); cp_commit();

    for (int i = 0; i < nk; i++) {
        cp_wait<2>();
        __syncthreads();
        if (i + 3 < nk) issue((i + 3) & 3, i + 3);
        cp_commit();

        const unsigned* as = &As[(i & 3) * GST_U32];
        const unsigned* bs = &Bs[(i & 3) * GST_U32];

        #pragma unroll
        for (int kg = 0; kg < 2; kg++) {
            unsigned afr[4][4], bfr[4][2];
            #pragma unroll
            for (int ii = 0; ii < 4; ii++) {
                int r = warpM * 64 + ii * 16 + groupID;
                afr[ii][0] = as[r * GSTRIDE + kg * 8 + tid4];
                afr[ii][1] = as[(r + 8) * GSTRIDE + kg * 8 + tid4];
                afr[ii][2] = as[r * GSTRIDE + kg * 8 + tid4 + 4];
                afr[ii][3] = as[(r + 8) * GSTRIDE + kg * 8 + tid4 + 4];
            }
            #pragma unroll
            for (int j = 0; j < 4; j++) {
                int cn = warpN * 32 + j * 8 + groupID;
                bfr[j][0] = bs[cn * GSTRIDE + kg * 8 + tid4];
                bfr[j][1] = bs[cn * GSTRIDE + kg * 8 + tid4 + 4];
            }
            #pragma unroll
            for (int ii = 0; ii < 4; ii++)
                #pragma unroll
                for (int j = 0; j < 4; j++)
                    mma16(acc[ii][j], afr[kg == 0 ? ii : ii][0] ? afr[ii] : afr[ii], bfr[j]);
        }
    }

    // epilogue
    float*  Cf = (float*)Cv;
    __half* Ch = (__half*)Cv;
    #pragma unroll
    for (int i = 0; i < 4; i++) {
        int r0 = mBase + warpM * 64 + i * 16 + groupID;
        int r1 = r0 + 8;
        #pragma unroll
        for (int j = 0; j < 4; j++) {
            int cn = nBase + warpN * 32 + j * 8 + tid4 * 2;
            float bv0, bv1;
            if (EPI == 1) {
                bv0 = (cn < 768) ? bias[cn] : ((cn < 1536) ? 0.f : bias2[cn - 1536]);
                int c1 = cn + 1;
                bv1 = (c1 < 768) ? bias[c1] : ((c1 < 1536) ? 0.f : bias2[c1 - 1536]);
            } else {
                bv0 = bias[cn]; bv1 = bias[cn + 1];
            }
            #pragma unroll
            for (int rr = 0; rr < 2; rr++) {
                int gm = rr ? r1 : r0;
                if (gm >= M) continue;
                size_t off = (size_t)gm * Nn + cn;
                float v0 = acc[i][j][rr * 2 + 0] + bv0;
                float v1 = acc[i][j][rr * 2 + 1] + bv1;
                if (EPI == 2) {
                    v0 = 0.5f * v0 * (1.f + erff(v0 * 0.70710678118654752f));
                    v1 = 0.5f * v1 * (1.f + erff(v1 * 0.70710678118654752f));
                    *(__half2*)&Ch[off] = __floats2half2_rn(v0, v1);
                } else if (EPI == 3) {
                    v0 += res[off]; v1 += res[off + 1];
                    float2 o; o.x = v0; o.y = v1;
                    *(float2*)&Cf[off] = o;
                } else {
                    float2 o; o.x = v0; o.y = v1;
                    *(float2*)&Cf[off] = o;
                }
            }
        }
    }
}

// ---------------- flash attention (tf32, unchanged except fp16 output) ----------------
#define KSTR 68
#define VSTR 72
#define PSTR 68
#define NCH  10
#define SKV_F (64*KSTR + 64*VSTR)
#define ATTN_SMEM ((2*SKV_F + 128*PSTR) * 4)

__global__ void __launch_bounds__(256, 2)
attn_kernel(const float* __restrict__ qkv, const float* __restrict__ rpbf,
            __half* __restrict__ out)
{
    extern __shared__ float sm[];
    float* sK0 = sm;
    float* sV0 = sm + 64 * KSTR;
    float* sK1 = sm + SKV_F;
    float* sV1 = sK1 + 64 * KSTR;
    float* sP  = sm + 2 * SKV_F;

    const int tid = threadIdx.x;
    const int warp = tid >> 5, lane = tid & 31;
    const int groupID = lane >> 2, tid4 = lane & 3;
    const int q0 = blockIdx.x * 128;
    const int h  = blockIdx.y;
    const int b  = blockIdx.z;
    const size_t qkv_base = (size_t)b * N_ * QKVD + h * 64;

    {
        const float* qsrc = qkv + qkv_base;
        #pragma unroll
        for (int p = 0; p < 8; p++) {
            int f4 = p * 256 + tid;
            int row = f4 >> 4;
            int cc = (f4 & 15) * 4;
            int n = q0 + row;
            bool v = n < N_;
            cp16(&sP[row * PSTR + cc], v ? (qsrc + (size_t)n * QKVD + cc) : qkv, v);
        }
        cp_commit();
    }

    auto issueKV = [&](int c) {
        float* kD = (c & 1) ? sK1 : sK0;
        float* vD = (c & 1) ? sV1 : sV0;
        const float* ks = qkv + qkv_base + 768;
        const float* vs = qkv + qkv_base + 1536;
        #pragma unroll
        for (int p = 0; p < 4; p++) {
            int f4 = p * 256 + tid;
            int row = f4 >> 4;
            int cc = (f4 & 15) * 4;
            int kk = c * 64 + row;
            bool v = kk < N_;
            cp16(&kD[row * KSTR + cc], v ? (ks + (size_t)kk * QKVD + cc) : qkv, v);
            cp16(&vD[row * VSTR + cc], v ? (vs + (size_t)kk * QKVD + cc) : qkv, v);
        }
        cp_commit();
    };

    issueKV(0);
    issueKV(1);

    cp_wait<2>();
    __syncthreads();
    unsigned aq[8][4];
    {
        const unsigned* sPu = (const unsigned*)sP;
        int r = warp * 16 + groupID;
        #pragma unroll
        for (int kg = 0; kg < 8; kg++) {
            aq[kg][0] = sPu[r * PSTR + kg * 8 + tid4];
            aq[kg][1] = sPu[(r + 8) * PSTR + kg * 8 + tid4];
            aq[kg][2] = sPu[r * PSTR + kg * 8 + tid4 + 4];
            aq[kg][3] = sPu[(r + 8) * PSTR + kg * 8 + tid4 + 4];
        }
    }
    __syncthreads();

    const int n0 = q0 + warp * 16 + groupID;
    const int n1 = n0 + 8;
    const float* rpb0 = rpbf + ((size_t)h * N_ + (n0 < N_ ? n0 : 0)) * N_;
    const float* rpb1 = rpbf + ((size_t)h * N_ + (n1 < N_ ? n1 : 0)) * N_;

    float m0 = -1e30f, m1 = -1e30f, l0 = 0.f, l1 = 0.f;
    float oacc[8][4];
    #pragma unroll
    for (int j = 0; j < 8; j++)
        #pragma unroll
        for (int r = 0; r < 4; r++) oacc[j][r] = 0.f;

    for (int c = 0; c < NCH; c++) {
        cp_wait<1>();
        __syncthreads();
        const unsigned* sKu = (const unsigned*)((c & 1) ? sK1 : sK0);
        const unsigned* sVu = (const unsigned*)((c & 1) ? sV1 : sV0);

        float sc[8][4];
        #pragma unroll
        for (int j = 0; j < 8; j++)
            #pragma unroll
            for (int r = 0; r < 4; r++) sc[j][r] = 0.f;
        #pragma unroll
        for (int kg = 0; kg < 8; kg++) {
            #pragma unroll
            for (int j = 0; j < 8; j++) {
                int kcol = j * 8 + groupID;
                unsigned bk[2];
                bk[0] = sKu[kcol * KSTR + kg * 8 + tid4];
                bk[1] = sKu[kcol * KSTR + kg * 8 + tid4 + 4];
                mma8(sc[j], aq[kg], bk);
            }
        }

        const int cbase = c * 64;
        float mx0 = m0, mx1 = m1;
        #pragma unroll
        for (int j = 0; j < 8; j++) {
            int col = cbase + j * 8 + tid4 * 2;
            bool v0 = col < N_, v1 = (col + 1) < N_;
            sc[j][0] = v0 ? sc[j][0] * SCALE_ + rpb0[col]     : -1e30f;
            sc[j][1] = v1 ? sc[j][1] * SCALE_ + rpb0[col + 1] : -1e30f;
            sc[j][2] = v0 ? sc[j][2] * SCALE_ + rpb1[col]     : -1e30f;
            sc[j][3] = v1 ? sc[j][3] * SCALE_ + rpb1[col + 1] : -1e30f;
            mx0 = fmaxf(mx0, fmaxf(sc[j][0], sc[j][1]));
            mx1 = fmaxf(mx1, fmaxf(sc[j][2], sc[j][3]));
        }
        #pragma unroll
        for (int o = 1; o <= 2; o <<= 1) {
            mx0 = fmaxf(mx0, __shfl_xor_sync(0xffffffffu, mx0, o));
            mx1 = fmaxf(mx1, __shfl_xor_sync(0xffffffffu, mx1, o));
        }
        float f0 = __expf(m0 - mx0), f1 = __expf(m1 - mx1);
        m0 = mx0; m1 = mx1;

        float rs0 = 0.f, rs1 = 0.f;
        {
            int rloc = warp * 16 + groupID;
            #pragma unroll
            for (int j = 0; j < 8; j++) {
                float p00 = __expf(sc[j][0] - m0);
                float p01 = __expf(sc[j][1] - m0);
                float p10 = __expf(sc[j][2] - m1);
                float p11 = __expf(sc[j][3] - m1);
                rs0 += p00 + p01; rs1 += p10 + p11;
                int col = j * 8 + tid4 * 2;
                float2 w0; w0.x = p00; w0.y = p01;
                float2 w1; w1.x = p10; w1.y = p11;
                *(float2*)&sP[rloc * PSTR + col] = w0;
                *(float2*)&sP[(rloc + 8) * PSTR + col] = w1;
            }
        }
        #pragma unroll
        for (int o = 1; o <= 2; o <<= 1) {
            rs0 += __shfl_xor_sync(0xffffffffu, rs0, o);
            rs1 += __shfl_xor_sync(0xffffffffu, rs1, o);
        }
        l0 = l0 * f0 + rs0;
        l1 = l1 * f1 + rs1;
        #pragma unroll
        for (int j = 0; j < 8; j++) {
            oacc[j][0] *= f0; oacc[j][1] *= f0;
            oacc[j][2] *= f1; oacc[j][3] *= f1;
        }
        __syncwarp();

        {
            const unsigned* sPu = (const unsigned*)sP;
            int rloc = warp * 16 + groupID;
            #pragma unroll
            for (int kg = 0; kg < 8; kg++) {
                unsigned ap[4];
                ap[0] = sPu[rloc * PSTR + kg * 8 + tid4];
                ap[1] = sPu[(rloc + 8) * PSTR + kg * 8 + tid4];
                ap[2] = sPu[rloc * PSTR + kg * 8 + tid4 + 4];
                ap[3] = sPu[(rloc + 8) * PSTR + kg * 8 + tid4 + 4];
                #pragma unroll
                for (int j = 0; j < 8; j++) {
                    int vcol = j * 8 + groupID;
                    unsigned bv[2];
                    bv[0] = sVu[(kg * 8 + tid4) * VSTR + vcol];
                    bv[1] = sVu[(kg * 8 + tid4 + 4) * VSTR + vcol];
                    mma8(oacc[j], ap, bv);
                }
            }
        }
        __syncthreads();
        if (c + 2 < NCH) issueKV(c + 2);
        else cp_commit();
    }

    {
        float inv0 = 1.f / l0, inv1 = 1.f / l1;
        #pragma unroll
        for (int j = 0; j < 8; j++) {
            int col = j * 8 + tid4 * 2;
            if (n0 < N_) {
                *(__half2*)&out[((size_t)b * N_ + n0) * DIM_ + h * 64 + col] =
                    __floats2half2_rn(oacc[j][0] * inv0, oacc[j][1] * inv0);
            }
            if (n1 < N_) {
                *(__half2*)&out[((size_t)b * N_ + n1) * DIM_ + h * 64 + col] =
                    __floats2half2_rn(oacc[j][2] * inv1, oacc[j][3] * inv1);
            }
        }
    }
}

// ---------------- launch ----------------
extern "C" void kernel_launch(void* const* d_in, const int* in_sizes, int n_in,
                              void* d_out, int out_size)
{
    const float* x     = (const float*)d_in[0];
    const float* n1g   = (const float*)d_in[1];
    const float* n1b   = (const float*)d_in[2];
    const float* qkvw  = (const float*)d_in[3];
    const float* qb    = (const float*)d_in[4];
    const float* vb    = (const float*)d_in[5];
    const float* rpbt  = (const float*)d_in[6];
    const float* projw = (const float*)d_in[7];
    const float* projb = (const float*)d_in[8];
    const float* n2g   = (const float*)d_in[9];
    const float* n2b   = (const float*)d_in[10];
    const float* fc1w  = (const float*)d_in[11];
    const float* fc1b  = (const float*)d_in[12];
    const float* fc2w  = (const float*)d_in[13];
    const float* fc2b  = (const float*)d_in[14];
    const int*   ridx  = (const int*)d_in[15];
    float* out = (float*)d_out;

    __half *ph, *patt, *pm, *pwqkv, *pwproj, *pwfc1, *pwfc2;
    float *pqkv, *prpb;
    cudaGetSymbolAddress((void**)&ph,    g_h);
    cudaGetSymbolAddress((void**)&pqkv,  g_qkv);
    cudaGetSymbolAddress((void**)&patt,  g_att);
    cudaGetSymbolAddress((void**)&pm,    g_m);
    cudaGetSymbolAddress((void**)&prpb,  g_rpbf);
    cudaGetSymbolAddress((void**)&pwqkv, g_wqkv);
    cudaGetSymbolAddress((void**)&pwproj,g_wproj);
    cudaGetSymbolAddress((void**)&pwfc1, g_wfc1);
    cudaGetSymbolAddress((void**)&pwfc2, g_wfc2);

    static bool attr_done = false;
    if (!attr_done) {
        cudaFuncSetAttribute(gemm_h<1>, cudaFuncAttributeMaxDynamicSharedMemorySize, GEMM_SMEM);
        cudaFuncSetAttribute(gemm_h<2>, cudaFuncAttributeMaxDynamicSharedMemorySize, GEMM_SMEM);
        cudaFuncSetAttribute(gemm_h<3>, cudaFuncAttributeMaxDynamicSharedMemorySize, GEMM_SMEM);
        cudaFuncSetAttribute(attn_kernel, cudaFuncAttributeMaxDynamicSharedMemorySize, ATTN_SMEM);
        attr_done = true;
    }

    // weight conversions (fp32 -> fp16)
    f2h_kernel<<<(QKVD * DIM_ / 4 + 255) / 256, 256>>>(qkvw,  pwqkv,  QKVD * DIM_ / 4);
    f2h_kernel<<<(DIM_ * DIM_ / 4 + 255) / 256, 256>>>(projw, pwproj, DIM_ * DIM_ / 4);
    f2h_kernel<<<(MLP_ * DIM_ / 4 + 255) / 256, 256>>>(fc1w,  pwfc1,  MLP_ * DIM_ / 4);
    f2h_kernel<<<(DIM_ * MLP_ / 4 + 255) / 256, 256>>>(fc2w,  pwfc2,  DIM_ * MLP_ / 4);

    const int mTiles = (MTOK + 127) / 128;

    ln_kernel<<<MTOK, 256>>>(x, n1g, n1b, ph);
    rpb_expand<<<(NH_ * N_ * N_ + 255) / 256, 256>>>(rpbt, ridx, prpb);
    gemm_h<1><<<dim3(QKVD / 128, mTiles), 256, GEMM_SMEM>>>(ph, pwqkv, pqkv, MTOK, QKVD, DIM_, qb, vb, nullptr);
    attn_kernel<<<dim3((N_ + 127) / 128, NH_, B_), 256, ATTN_SMEM>>>(pqkv, prpb, patt);
    gemm_h<3><<<dim3(DIM_ / 128, mTiles), 256, GEMM_SMEM>>>(patt, pwproj, out, MTOK, DIM_, DIM_, projb, nullptr, x);
    ln_kernel<<<MTOK, 256>>>(out, n2g, n2b, ph);
    gemm_h<2><<<dim3(MLP_ / 128, mTiles), 256, GEMM_SMEM>>>(ph, pwfc1, pm, MTOK, MLP_, DIM_, fc1b, nullptr, nullptr);
    gemm_h<3><<<dim3(DIM_ / 128, mTiles), 256, GEMM_SMEM>>>(pm, pwfc2, out, MTOK, DIM_, MLP_, fc2b, nullptr, out);
}

// round 9
// speedup vs baseline: 1.8549x; 1.1477x over previous
#include <cuda_runtime.h>
#include <cuda_fp16.h>
#include <math.h>

#define B_    32
#define N_    577
#define DIM_  768
#define NH_   12
#define HD_   64
#define MLP_  3072
#define MTOK  (B_*N_)          /* 18464 */
#define QKVD  (3*DIM_)         /* 2304 */
#define SCALE_ 0.125f

// ---------------- scratch ----------------
__device__ __align__(16) __half g_h   [(size_t)MTOK * DIM_];    // LN out (fp16)
__device__ __align__(16) __half g_qkv [(size_t)MTOK * QKVD];    // qkv (fp16)
__device__ __align__(16) __half g_att [(size_t)MTOK * DIM_];    // attn out (fp16)
__device__ __align__(16) __half g_m   [(size_t)MTOK * MLP_];    // MLP hidden (fp16)
__device__ __align__(16) float  g_rpbf[(size_t)NH_ * N_ * N_];
// fp16 weight copies
__device__ __align__(16) __half g_wqkv[(size_t)QKVD * DIM_];
__device__ __align__(16) __half g_wproj[(size_t)DIM_ * DIM_];
__device__ __align__(16) __half g_wfc1[(size_t)MLP_ * DIM_];
__device__ __align__(16) __half g_wfc2[(size_t)DIM_ * MLP_];

// ---------------- helpers ----------------
__device__ __forceinline__ void cp16(void* dst, const void* src, bool valid) {
    unsigned d = (unsigned)__cvta_generic_to_shared(dst);
    int sz = valid ? 16 : 0;
    asm volatile("cp.async.cg.shared.global [%0], [%1], 16, %2;\n" :: "r"(d), "l"(src), "r"(sz));
}
__device__ __forceinline__ void cp_commit() { asm volatile("cp.async.commit_group;\n"); }
template<int Nw> __device__ __forceinline__ void cp_wait() {
    asm volatile("cp.async.wait_group %0;\n" :: "n"(Nw));
}
__device__ __forceinline__ void mma16(float* c, const unsigned* a, const unsigned* b) {
    asm volatile(
        "mma.sync.aligned.m16n8k16.row.col.f32.f16.f16.f32 "
        "{%0,%1,%2,%3},{%4,%5,%6,%7},{%8,%9},{%0,%1,%2,%3};"
        : "+f"(c[0]), "+f"(c[1]), "+f"(c[2]), "+f"(c[3])
        : "r"(a[0]), "r"(a[1]), "r"(a[2]), "r"(a[3]), "r"(b[0]), "r"(b[1]));
}
__device__ __forceinline__ void ldmat4t(unsigned* d, const __half* p) {
    unsigned a = (unsigned)__cvta_generic_to_shared(p);
    asm volatile("ldmatrix.sync.aligned.m8n8.x4.trans.shared.b16 {%0,%1,%2,%3}, [%4];"
        : "=r"(d[0]), "=r"(d[1]), "=r"(d[2]), "=r"(d[3]) : "r"(a));
}
__device__ __forceinline__ unsigned packh2(float a, float b) {
    __half2 h = __floats2half2_rn(a, b);
    return *(unsigned*)&h;
}

// ---------------- fp32 -> fp16 weight convert ----------------
__global__ void f2h_kernel(const float* __restrict__ s, __half* __restrict__ d, int n4)
{
    int i = blockIdx.x * 256 + threadIdx.x;
    if (i >= n4) return;
    float4 v = *(const float4*)(s + (size_t)i * 4);
    __half2 lo = __floats2half2_rn(v.x, v.y);
    __half2 hi = __floats2half2_rn(v.z, v.w);
    *(__half2*)(d + (size_t)i * 4)     = lo;
    *(__half2*)(d + (size_t)i * 4 + 2) = hi;
}

// ---------------- LayerNorm (fp32 in -> fp16 out) ----------------
__global__ void __launch_bounds__(256)
ln_kernel(const float* __restrict__ in, const float* __restrict__ g,
          const float* __restrict__ bta, __half* __restrict__ out)
{
    __shared__ float red[16];
    __shared__ float s_stats[2];
    const int row = blockIdx.x;
    const int tid = threadIdx.x;
    const float* p = in + (size_t)row * DIM_;
    float v0 = p[tid], v1 = p[tid + 256], v2 = p[tid + 512];
    float s1 = v0 + v1 + v2;
    float s2 = v0*v0 + v1*v1 + v2*v2;
    #pragma unroll
    for (int o = 16; o > 0; o >>= 1) {
        s1 += __shfl_xor_sync(0xffffffffu, s1, o);
        s2 += __shfl_xor_sync(0xffffffffu, s2, o);
    }
    const int warp = tid >> 5, lane = tid & 31;
    if (lane == 0) { red[warp] = s1; red[warp + 8] = s2; }
    __syncthreads();
    if (tid == 0) {
        float t1 = 0.f, t2 = 0.f;
        #pragma unroll
        for (int w = 0; w < 8; w++) { t1 += red[w]; t2 += red[w + 8]; }
        float mean = t1 * (1.f / DIM_);
        float var  = t2 * (1.f / DIM_) - mean * mean;
        s_stats[0] = mean;
        s_stats[1] = rsqrtf(var + 1e-6f);
    }
    __syncthreads();
    const float mean = s_stats[0], inv = s_stats[1];
    __half* o = out + (size_t)row * DIM_;
    o[tid]       = __float2half_rn((v0 - mean) * inv * g[tid]       + bta[tid]);
    o[tid + 256] = __float2half_rn((v1 - mean) * inv * g[tid + 256] + bta[tid + 256]);
    o[tid + 512] = __float2half_rn((v2 - mean) * inv * g[tid + 512] + bta[tid + 512]);
}

// ---------------- rel-pos bias expand ----------------
__global__ void rpb_expand(const float* __restrict__ table, const int* __restrict__ relidx,
                           float* __restrict__ out)
{
    int t = blockIdx.x * 256 + threadIdx.x;
    const int total = NH_ * N_ * N_;
    if (t >= total) return;
    int h = t / (N_ * N_);
    int r = t - h * (N_ * N_);
    out[t] = table[relidx[r] * NH_ + h];
}

// ---------------- FP16 tensor-core GEMM NT, 4-stage cp.async ----------------
// C[M,Nn] = A[M,K] @ Bw[Nn,K]^T + epilogue
// EPI 1: qkv concat bias -> fp16 out
// EPI 2: gelu(v+bias)    -> fp16 out
// EPI 3: res + v + bias  -> fp32 out
#define GSTAGES 4
#define GSTRIDE 20                       /* u32 per row (32 halves data + 8 pad) */
#define GST_U32 (128 * GSTRIDE)
#define GEMM_SMEM (GSTAGES * GST_U32 * 2 * 4)   /* 81920 B */

template<int EPI>
__global__ void __launch_bounds__(256, 2)
gemm_h(const __half* __restrict__ A, const __half* __restrict__ Bw,
       void* __restrict__ Cv, int M, int Nn, int K,
       const float* __restrict__ bias, const float* __restrict__ bias2,
       const float* __restrict__ res)
{
    extern __shared__ unsigned smu[];
    unsigned* As = smu;
    unsigned* Bs = smu + GSTAGES * GST_U32;

    const int tid = threadIdx.x;
    const int warp = tid >> 5, lane = tid & 31;
    const int groupID = lane >> 2, tid4 = lane & 3;
    const int warpM = warp & 1, warpN = warp >> 1;
    const int mBase = blockIdx.y * 128;
    const int nBase = blockIdx.x * 128;

    const int lr  = tid >> 1;
    const int c0h = (tid & 1) * 16;

    const bool avok = (mBase + lr) < M;
    const __half* Ap = A  + (size_t)(mBase + lr) * K + c0h;
    const __half* Bp = Bw + (size_t)(nBase + lr) * K + c0h;

    float acc[4][4][4];
    #pragma unroll
    for (int i = 0; i < 4; i++)
        #pragma unroll
        for (int j = 0; j < 4; j++)
            #pragma unroll
            for (int r = 0; r < 4; r++) acc[i][j][r] = 0.f;

    const int nk = K >> 5;

    auto issue = [&](int s, int ks) {
        unsigned* ad = &As[s * GST_U32 + lr * GSTRIDE + (c0h >> 1)];
        unsigned* bd = &Bs[s * GST_U32 + lr * GSTRIDE + (c0h >> 1)];
        const __half* ap = Ap + ks * 32;
        const __half* bp = Bp + ks * 32;
        cp16(ad,     avok ? ap     : (const __half*)A, avok);
        cp16(ad + 4, avok ? ap + 8 : (const __half*)A, avok);
        cp16(bd,     bp,     true);
        cp16(bd + 4, bp + 8, true);
    };

    issue(0, 0); cp_commit();
    issue(1, 1); cp_commit();
    issue(2, 2); cp_commit();

    for (int i = 0; i < nk; i++) {
        cp_wait<2>();
        __syncthreads();
        if (i + 3 < nk) issue((i + 3) & 3, i + 3);
        cp_commit();

        const unsigned* as = &As[(i & 3) * GST_U32];
        const unsigned* bs = &Bs[(i & 3) * GST_U32];

        #pragma unroll
        for (int kg = 0; kg < 2; kg++) {
            unsigned afr[4][4], bfr[4][2];
            #pragma unroll
            for (int ii = 0; ii < 4; ii++) {
                int r = warpM * 64 + ii * 16 + groupID;
                afr[ii][0] = as[r * GSTRIDE + kg * 8 + tid4];
                afr[ii][1] = as[(r + 8) * GSTRIDE + kg * 8 + tid4];
                afr[ii][2] = as[r * GSTRIDE + kg * 8 + tid4 + 4];
                afr[ii][3] = as[(r + 8) * GSTRIDE + kg * 8 + tid4 + 4];
            }
            #pragma unroll
            for (int j = 0; j < 4; j++) {
                int cn = warpN * 32 + j * 8 + groupID;
                bfr[j][0] = bs[cn * GSTRIDE + kg * 8 + tid4];
                bfr[j][1] = bs[cn * GSTRIDE + kg * 8 + tid4 + 4];
            }
            #pragma unroll
            for (int ii = 0; ii < 4; ii++)
                #pragma unroll
                for (int j = 0; j < 4; j++)
                    mma16(acc[ii][j], afr[ii], bfr[j]);
        }
    }

    // epilogue
    float*  Cf = (float*)Cv;
    __half* Ch = (__half*)Cv;
    #pragma unroll
    for (int i = 0; i < 4; i++) {
        int r0 = mBase + warpM * 64 + i * 16 + groupID;
        int r1 = r0 + 8;
        #pragma unroll
        for (int j = 0; j < 4; j++) {
            int cn = nBase + warpN * 32 + j * 8 + tid4 * 2;
            float bv0, bv1;
            if (EPI == 1) {
                bv0 = (cn < 768) ? bias[cn] : ((cn < 1536) ? 0.f : bias2[cn - 1536]);
                int c1 = cn + 1;
                bv1 = (c1 < 768) ? bias[c1] : ((c1 < 1536) ? 0.f : bias2[c1 - 1536]);
            } else {
                bv0 = bias[cn]; bv1 = bias[cn + 1];
            }
            #pragma unroll
            for (int rr = 0; rr < 2; rr++) {
                int gm = rr ? r1 : r0;
                if (gm >= M) continue;
                size_t off = (size_t)gm * Nn + cn;
                float v0 = acc[i][j][rr * 2 + 0] + bv0;
                float v1 = acc[i][j][rr * 2 + 1] + bv1;
                if (EPI == 1) {
                    *(__half2*)&Ch[off] = __floats2half2_rn(v0, v1);
                } else if (EPI == 2) {
                    v0 = 0.5f * v0 * (1.f + erff(v0 * 0.70710678118654752f));
                    v1 = 0.5f * v1 * (1.f + erff(v1 * 0.70710678118654752f));
                    *(__half2*)&Ch[off] = __floats2half2_rn(v0, v1);
                } else {
                    v0 += res[off]; v1 += res[off + 1];
                    float2 o; o.x = v0; o.y = v1;
                    *(float2*)&Cf[off] = o;
                }
            }
        }
    }
}

// ---------------- fp16 flash attention: 128 q/block, P stays in registers ----------------
#define QSTR 72   /* halves */
#define KSTR 72
#define VSTR 72
#define NCH  10
#define ATTN_SMEM ((128*QSTR + 4*64*KSTR) * 2)   /* 55296 B */

__global__ void __launch_bounds__(256, 2)
attn_kernel(const __half* __restrict__ qkv, const float* __restrict__ rpbf,
            __half* __restrict__ out)
{
    extern __shared__ __half smh[];
    __half* sQ  = smh;
    __half* sK0 = smh + 128 * QSTR;
    __half* sV0 = sK0 + 64 * KSTR;
    __half* sK1 = sV0 + 64 * VSTR;
    __half* sV1 = sK1 + 64 * KSTR;

    const int tid = threadIdx.x;
    const int warp = tid >> 5, lane = tid & 31;
    const int groupID = lane >> 2, tid4 = lane & 3;
    const int q0 = blockIdx.x * 128;
    const int h  = blockIdx.y;
    const int b  = blockIdx.z;
    const size_t qkv_base = (size_t)b * N_ * QKVD + h * 64;

    // Q tile: 128 rows x 64 halves (8 x 16B per row)
    {
        const __half* qsrc = qkv + qkv_base;
        #pragma unroll
        for (int p = 0; p < 4; p++) {
            int u = p * 256 + tid;          // 0..1023
            int row = u >> 3;
            int cc = (u & 7) * 8;           // half offset
            int n = q0 + row;
            bool v = n < N_;
            cp16(&sQ[row * QSTR + cc], v ? (qsrc + (size_t)n * QKVD + cc) : qkv, v);
        }
        cp_commit();
    }

    auto issueKV = [&](int c) {
        __half* kD = (c & 1) ? sK1 : sK0;
        __half* vD = (c & 1) ? sV1 : sV0;
        const __half* ks = qkv + qkv_base + 768;
        const __half* vs = qkv + qkv_base + 1536;
        #pragma unroll
        for (int p = 0; p < 2; p++) {
            int u = p * 256 + tid;          // 0..511
            int row = u >> 3;
            int cc = (u & 7) * 8;
            int kk = c * 64 + row;
            bool v = kk < N_;
            cp16(&kD[row * KSTR + cc], v ? (ks + (size_t)kk * QKVD + cc) : qkv, v);
            cp16(&vD[row * VSTR + cc], v ? (vs + (size_t)kk * QKVD + cc) : qkv, v);
        }
        cp_commit();
    };

    issueKV(0);
    issueKV(1);

    // wait for Q, read A-fragments (validated GEMM layout)
    cp_wait<2>();
    __syncthreads();
    unsigned aq[4][4];
    {
        const unsigned* qrow  = (const unsigned*)(sQ + (warp * 16 + groupID) * QSTR);
        const unsigned* qrow8 = (const unsigned*)(sQ + (warp * 16 + groupID + 8) * QSTR);
        #pragma unroll
        for (int ks = 0; ks < 4; ks++) {
            aq[ks][0] = qrow [ks * 8 + tid4];
            aq[ks][1] = qrow8[ks * 8 + tid4];
            aq[ks][2] = qrow [ks * 8 + tid4 + 4];
            aq[ks][3] = qrow8[ks * 8 + tid4 + 4];
        }
    }

    const int n0 = q0 + warp * 16 + groupID;
    const int n1 = n0 + 8;
    const float* rpb0 = rpbf + ((size_t)h * N_ + (n0 < N_ ? n0 : 0)) * N_;
    const float* rpb1 = rpbf + ((size_t)h * N_ + (n1 < N_ ? n1 : 0)) * N_;

    float m0 = -1e30f, m1 = -1e30f, l0 = 0.f, l1 = 0.f;
    float oacc[8][4];
    #pragma unroll
    for (int j = 0; j < 8; j++)
        #pragma unroll
        for (int r = 0; r < 4; r++) oacc[j][r] = 0.f;

    // ldmatrix per-lane source row/col (within a 16x16 V sub-tile)
    const int lmrow = (lane & 7) + ((lane >> 3) & 1) * 8;
    const int lmcol = (lane >> 4) * 8;

    for (int c = 0; c < NCH; c++) {
        cp_wait<1>();
        __syncthreads();
        const __half* sK = (c & 1) ? sK1 : sK0;
        const __half* sV = (c & 1) ? sV1 : sV0;

        // ---- S = Q K^T (fp32 accum) ----
        float sc[8][4];
        #pragma unroll
        for (int j = 0; j < 8; j++)
            #pragma unroll
            for (int r = 0; r < 4; r++) sc[j][r] = 0.f;
        #pragma unroll
        for (int j = 0; j < 8; j++) {
            const unsigned* krow = (const unsigned*)(sK + (j * 8 + groupID) * KSTR);
            #pragma unroll
            for (int ks = 0; ks < 4; ks++) {
                unsigned bk[2];
                bk[0] = krow[ks * 8 + tid4];
                bk[1] = krow[ks * 8 + tid4 + 4];
                mma16(sc[j], aq[ks], bk);
            }
        }

        // ---- scale + rpb + mask; online softmax ----
        const int cbase = c * 64;
        float mx0 = m0, mx1 = m1;
        #pragma unroll
        for (int j = 0; j < 8; j++) {
            int col = cbase + j * 8 + tid4 * 2;
            bool v0 = col < N_, v1 = (col + 1) < N_;
            sc[j][0] = v0 ? sc[j][0] * SCALE_ + rpb0[col]     : -1e30f;
            sc[j][1] = v1 ? sc[j][1] * SCALE_ + rpb0[col + 1] : -1e30f;
            sc[j][2] = v0 ? sc[j][2] * SCALE_ + rpb1[col]     : -1e30f;
            sc[j][3] = v1 ? sc[j][3] * SCALE_ + rpb1[col + 1] : -1e30f;
            mx0 = fmaxf(mx0, fmaxf(sc[j][0], sc[j][1]));
            mx1 = fmaxf(mx1, fmaxf(sc[j][2], sc[j][3]));
        }
        #pragma unroll
        for (int o = 1; o <= 2; o <<= 1) {
            mx0 = fmaxf(mx0, __shfl_xor_sync(0xffffffffu, mx0, o));
            mx1 = fmaxf(mx1, __shfl_xor_sync(0xffffffffu, mx1, o));
        }
        float f0 = __expf(m0 - mx0), f1 = __expf(m1 - mx1);
        m0 = mx0; m1 = mx1;

        float rs0 = 0.f, rs1 = 0.f;
        #pragma unroll
        for (int j = 0; j < 8; j++) {
            sc[j][0] = __expf(sc[j][0] - m0);
            sc[j][1] = __expf(sc[j][1] - m0);
            sc[j][2] = __expf(sc[j][2] - m1);
            sc[j][3] = __expf(sc[j][3] - m1);
            rs0 += sc[j][0] + sc[j][1];
            rs1 += sc[j][2] + sc[j][3];
        }
        #pragma unroll
        for (int o = 1; o <= 2; o <<= 1) {
            rs0 += __shfl_xor_sync(0xffffffffu, rs0, o);
            rs1 += __shfl_xor_sync(0xffffffffu, rs1, o);
        }
        l0 = l0 * f0 + rs0;
        l1 = l1 * f1 + rs1;
        #pragma unroll
        for (int j = 0; j < 8; j++) {
            oacc[j][0] *= f0; oacc[j][1] *= f0;
            oacc[j][2] *= f1; oacc[j][3] *= f1;
        }

        // ---- P fragments from registers (C-layout == A-layout) ----
        unsigned ap[4][4];
        #pragma unroll
        for (int ks = 0; ks < 4; ks++) {
            ap[ks][0] = packh2(sc[2*ks][0],   sc[2*ks][1]);
            ap[ks][1] = packh2(sc[2*ks][2],   sc[2*ks][3]);
            ap[ks][2] = packh2(sc[2*ks+1][0], sc[2*ks+1][1]);
            ap[ks][3] = packh2(sc[2*ks+1][2], sc[2*ks+1][3]);
        }

        // ---- O += P V  (V B-fragments via ldmatrix.trans) ----
        #pragma unroll
        for (int ks = 0; ks < 4; ks++) {
            #pragma unroll
            for (int n16 = 0; n16 < 4; n16++) {
                unsigned bv[4];
                ldmat4t(bv, sV + (ks * 16 + lmrow) * VSTR + n16 * 16 + lmcol);
                mma16(oacc[2*n16],     ap[ks], bv);
                mma16(oacc[2*n16 + 1], ap[ks], bv + 2);
            }
        }

        __syncthreads();
        if (c + 2 < NCH) issueKV(c + 2);
        else cp_commit();
    }

    // ---- normalize + store ----
    {
        float inv0 = 1.f / l0, inv1 = 1.f / l1;
        #pragma unroll
        for (int j = 0; j < 8; j++) {
            int col = j * 8 + tid4 * 2;
            if (n0 < N_) {
                *(__half2*)&out[((size_t)b * N_ + n0) * DIM_ + h * 64 + col] =
                    __floats2half2_rn(oacc[j][0] * inv0, oacc[j][1] * inv0);
            }
            if (n1 < N_) {
                *(__half2*)&out[((size_t)b * N_ + n1) * DIM_ + h * 64 + col] =
                    __floats2half2_rn(oacc[j][2] * inv1, oacc[j][3] * inv1);
            }
        }
    }
}

// ---------------- launch ----------------
extern "C" void kernel_launch(void* const* d_in, const int* in_sizes, int n_in,
                              void* d_out, int out_size)
{
    const float* x     = (const float*)d_in[0];
    const float* n1g   = (const float*)d_in[1];
    const float* n1b   = (const float*)d_in[2];
    const float* qkvw  = (const float*)d_in[3];
    const float* qb    = (const float*)d_in[4];
    const float* vb    = (const float*)d_in[5];
    const float* rpbt  = (const float*)d_in[6];
    const float* projw = (const float*)d_in[7];
    const float* projb = (const float*)d_in[8];
    const float* n2g   = (const float*)d_in[9];
    const float* n2b   = (const float*)d_in[10];
    const float* fc1w  = (const float*)d_in[11];
    const float* fc1b  = (const float*)d_in[12];
    const float* fc2w  = (const float*)d_in[13];
    const float* fc2b  = (const float*)d_in[14];
    const int*   ridx  = (const int*)d_in[15];
    float* out = (float*)d_out;

    __half *ph, *pqkv, *patt, *pm, *pwqkv, *pwproj, *pwfc1, *pwfc2;
    float *prpb;
    cudaGetSymbolAddress((void**)&ph,    g_h);
    cudaGetSymbolAddress((void**)&pqkv,  g_qkv);
    cudaGetSymbolAddress((void**)&patt,  g_att);
    cudaGetSymbolAddress((void**)&pm,    g_m);
    cudaGetSymbolAddress((void**)&prpb,  g_rpbf);
    cudaGetSymbolAddress((void**)&pwqkv, g_wqkv);
    cudaGetSymbolAddress((void**)&pwproj,g_wproj);
    cudaGetSymbolAddress((void**)&pwfc1, g_wfc1);
    cudaGetSymbolAddress((void**)&pwfc2, g_wfc2);

    static bool attr_done = false;
    if (!attr_done) {
        cudaFuncSetAttribute(gemm_h<1>, cudaFuncAttributeMaxDynamicSharedMemorySize, GEMM_SMEM);
        cudaFuncSetAttribute(gemm_h<2>, cudaFuncAttributeMaxDynamicSharedMemorySize, GEMM_SMEM);
        cudaFuncSetAttribute(gemm_h<3>, cudaFuncAttributeMaxDynamicSharedMemorySize, GEMM_SMEM);
        cudaFuncSetAttribute(attn_kernel, cudaFuncAttributeMaxDynamicSharedMemorySize, ATTN_SMEM);
        attr_done = true;
    }

    // weight conversions (fp32 -> fp16)
    f2h_kernel<<<(QKVD * DIM_ / 4 + 255) / 256, 256>>>(qkvw,  pwqkv,  QKVD * DIM_ / 4);
    f2h_kernel<<<(DIM_ * DIM_ / 4 + 255) / 256, 256>>>(projw, pwproj, DIM_ * DIM_ / 4);
    f2h_kernel<<<(MLP_ * DIM_ / 4 + 255) / 256, 256>>>(fc1w,  pwfc1,  MLP_ * DIM_ / 4);
    f2h_kernel<<<(DIM_ * MLP_ / 4 + 255) / 256, 256>>>(fc2w,  pwfc2,  DIM_ * MLP_ / 4);

    const int mTiles = (MTOK + 127) / 128;

    ln_kernel<<<MTOK, 256>>>(x, n1g, n1b, ph);
    rpb_expand<<<(NH_ * N_ * N_ + 255) / 256, 256>>>(rpbt, ridx, prpb);
    gemm_h<1><<<dim3(QKVD / 128, mTiles), 256, GEMM_SMEM>>>(ph, pwqkv, pqkv, MTOK, QKVD, DIM_, qb, vb, nullptr);
    attn_kernel<<<dim3((N_ + 127) / 128, NH_, B_), 256, ATTN_SMEM>>>(pqkv, prpb, patt);
    gemm_h<3><<<dim3(DIM_ / 128, mTiles), 256, GEMM_SMEM>>>(patt, pwproj, out, MTOK, DIM_, DIM_, projb, nullptr, x);
    ln_kernel<<<MTOK, 256>>>(out, n2g, n2b, ph);
    gemm_h<2><<<dim3(MLP_ / 128, mTiles), 256, GEMM_SMEM>>>(ph, pwfc1, pm, MTOK, MLP_, DIM_, fc1b, nullptr, nullptr);
    gemm_h<3><<<dim3(DIM_ / 128, mTiles), 256, GEMM_SMEM>>>(pm, pwfc2, out, MTOK, DIM_, MLP_, fc2b, nullptr, out);
}

// round 10
// speedup vs baseline: 1.8572x; 1.0013x over previous
#include <cuda_runtime.h>
#include <cuda_fp16.h>
#include <math.h>

#define B_    32
#define N_    577
#define DIM_  768
#define NH_   12
#define HD_   64
#define MLP_  3072
#define MTOK  (B_*N_)          /* 18464 */
#define QKVD  (3*DIM_)         /* 2304 */
#define SCALE_ 0.125f

// ---------------- scratch ----------------
__device__ __align__(16) __half g_h   [(size_t)MTOK * DIM_];    // LN out (fp16)
__device__ __align__(16) __half g_qkv [(size_t)MTOK * QKVD];    // qkv (fp16)
__device__ __align__(16) __half g_att [(size_t)MTOK * DIM_];    // attn out (fp16)
__device__ __align__(16) __half g_m   [(size_t)MTOK * MLP_];    // MLP hidden (fp16)
__device__ __align__(16) float  g_rpbf[(size_t)NH_ * N_ * N_];
// fp16 weight copies
__device__ __align__(16) __half g_wqkv[(size_t)QKVD * DIM_];
__device__ __align__(16) __half g_wproj[(size_t)DIM_ * DIM_];
__device__ __align__(16) __half g_wfc1[(size_t)MLP_ * DIM_];
__device__ __align__(16) __half g_wfc2[(size_t)DIM_ * MLP_];

// ---------------- helpers ----------------
__device__ __forceinline__ void cp16(void* dst, const void* src, bool valid) {
    unsigned d = (unsigned)__cvta_generic_to_shared(dst);
    int sz = valid ? 16 : 0;
    asm volatile("cp.async.cg.shared.global [%0], [%1], 16, %2;\n" :: "r"(d), "l"(src), "r"(sz));
}
__device__ __forceinline__ void cp_commit() { asm volatile("cp.async.commit_group;\n"); }
template<int Nw> __device__ __forceinline__ void cp_wait() {
    asm volatile("cp.async.wait_group %0;\n" :: "n"(Nw));
}
__device__ __forceinline__ void mma16(float* c, const unsigned* a, const unsigned* b) {
    asm volatile(
        "mma.sync.aligned.m16n8k16.row.col.f32.f16.f16.f32 "
        "{%0,%1,%2,%3},{%4,%5,%6,%7},{%8,%9},{%0,%1,%2,%3};"
        : "+f"(c[0]), "+f"(c[1]), "+f"(c[2]), "+f"(c[3])
        : "r"(a[0]), "r"(a[1]), "r"(a[2]), "r"(a[3]), "r"(b[0]), "r"(b[1]));
}
__device__ __forceinline__ void ldmat4t(unsigned* d, const __half* p) {
    unsigned a = (unsigned)__cvta_generic_to_shared(p);
    asm volatile("ldmatrix.sync.aligned.m8n8.x4.trans.shared.b16 {%0,%1,%2,%3}, [%4];"
        : "=r"(d[0]), "=r"(d[1]), "=r"(d[2]), "=r"(d[3]) : "r"(a));
}
__device__ __forceinline__ unsigned packh2(float a, float b) {
    __half2 h = __floats2half2_rn(a, b);
    return *(unsigned*)&h;
}

// ---------------- fp32 -> fp16 weight convert ----------------
__global__ void f2h_kernel(const float* __restrict__ s, __half* __restrict__ d, int n4)
{
    int i = blockIdx.x * 256 + threadIdx.x;
    if (i >= n4) return;
    float4 v = *(const float4*)(s + (size_t)i * 4);
    __half2 lo = __floats2half2_rn(v.x, v.y);
    __half2 hi = __floats2half2_rn(v.z, v.w);
    *(__half2*)(d + (size_t)i * 4)     = lo;
    *(__half2*)(d + (size_t)i * 4 + 2) = hi;
}

// ---------------- LayerNorm (fp32 in -> fp16 out) ----------------
__global__ void __launch_bounds__(256)
ln_kernel(const float* __restrict__ in, const float* __restrict__ g,
          const float* __restrict__ bta, __half* __restrict__ out)
{
    __shared__ float red[16];
    __shared__ float s_stats[2];
    const int row = blockIdx.x;
    const int tid = threadIdx.x;
    const float* p = in + (size_t)row * DIM_;
    float v0 = p[tid], v1 = p[tid + 256], v2 = p[tid + 512];
    float s1 = v0 + v1 + v2;
    float s2 = v0*v0 + v1*v1 + v2*v2;
    #pragma unroll
    for (int o = 16; o > 0; o >>= 1) {
        s1 += __shfl_xor_sync(0xffffffffu, s1, o);
        s2 += __shfl_xor_sync(0xffffffffu, s2, o);
    }
    const int warp = tid >> 5, lane = tid & 31;
    if (lane == 0) { red[warp] = s1; red[warp + 8] = s2; }
    __syncthreads();
    if (tid == 0) {
        float t1 = 0.f, t2 = 0.f;
        #pragma unroll
        for (int w = 0; w < 8; w++) { t1 += red[w]; t2 += red[w + 8]; }
        float mean = t1 * (1.f / DIM_);
        float var  = t2 * (1.f / DIM_) - mean * mean;
        s_stats[0] = mean;
        s_stats[1] = rsqrtf(var + 1e-6f);
    }
    __syncthreads();
    const float mean = s_stats[0], inv = s_stats[1];
    __half* o = out + (size_t)row * DIM_;
    o[tid]       = __float2half_rn((v0 - mean) * inv * g[tid]       + bta[tid]);
    o[tid + 256] = __float2half_rn((v1 - mean) * inv * g[tid + 256] + bta[tid + 256]);
    o[tid + 512] = __float2half_rn((v2 - mean) * inv * g[tid + 512] + bta[tid + 512]);
}

// ---------------- rel-pos bias expand ----------------
__global__ void rpb_expand(const float* __restrict__ table, const int* __restrict__ relidx,
                           float* __restrict__ out)
{
    int t = blockIdx.x * 256 + threadIdx.x;
    const int total = NH_ * N_ * N_;
    if (t >= total) return;
    int h = t / (N_ * N_);
    int r = t - h * (N_ * N_);
    out[t] = table[relidx[r] * NH_ + h];
}

// ---------------- FP16 tensor-core GEMM NT, 4-stage cp.async ----------------
// C[M,Nn] = A[M,K] @ Bw[Nn,K]^T + epilogue
// EPI 1: qkv concat bias -> fp16 out
// EPI 2: gelu(v+bias)    -> fp16 out
// EPI 3: res + v + bias  -> fp32 out
#define GSTAGES 4
#define GSTRIDE 20                       /* u32 per row (32 halves data + 8 pad) */
#define GST_U32 (128 * GSTRIDE)
#define GEMM_SMEM (GSTAGES * GST_U32 * 2 * 4)   /* 81920 B */

template<int EPI>
__global__ void __launch_bounds__(256, 2)
gemm_h(const __half* __restrict__ A, const __half* __restrict__ Bw,
       void* __restrict__ Cv, int M, int Nn, int K,
       const float* __restrict__ bias, const float* __restrict__ bias2,
       const float* __restrict__ res)
{
    extern __shared__ unsigned smu[];
    unsigned* As = smu;
    unsigned* Bs = smu + GSTAGES * GST_U32;

    const int tid = threadIdx.x;
    const int warp = tid >> 5, lane = tid & 31;
    const int groupID = lane >> 2, tid4 = lane & 3;
    const int warpM = warp & 1, warpN = warp >> 1;
    const int mBase = blockIdx.y * 128;
    const int nBase = blockIdx.x * 128;

    const int lr  = tid >> 1;
    const int c0h = (tid & 1) * 16;

    const bool avok = (mBase + lr) < M;
    const __half* Ap = A  + (size_t)(mBase + lr) * K + c0h;
    const __half* Bp = Bw + (size_t)(nBase + lr) * K + c0h;

    float acc[4][4][4];
    #pragma unroll
    for (int i = 0; i < 4; i++)
        #pragma unroll
        for (int j = 0; j < 4; j++)
            #pragma unroll
            for (int r = 0; r < 4; r++) acc[i][j][r] = 0.f;

    const int nk = K >> 5;

    auto issue = [&](int s, int ks) {
        unsigned* ad = &As[s * GST_U32 + lr * GSTRIDE + (c0h >> 1)];
        unsigned* bd = &Bs[s * GST_U32 + lr * GSTRIDE + (c0h >> 1)];
        const __half* ap = Ap + ks * 32;
        const __half* bp = Bp + ks * 32;
        cp16(ad,     avok ? ap     : (const __half*)A, avok);
        cp16(ad + 4, avok ? ap + 8 : (const __half*)A, avok);
        cp16(bd,     bp,     true);
        cp16(bd + 4, bp + 8, true);
    };

    issue(0, 0); cp_commit();
    issue(1, 1); cp_commit();
    issue(2, 2); cp_commit();

    for (int i = 0; i < nk; i++) {
        cp_wait<2>();
        __syncthreads();
        if (i + 3 < nk) issue((i + 3) & 3, i + 3);
        cp_commit();

        const unsigned* as = &As[(i & 3) * GST_U32];
        const unsigned* bs = &Bs[(i & 3) * GST_U32];

        #pragma unroll
        for (int kg = 0; kg < 2; kg++) {
            unsigned afr[4][4], bfr[4][2];
            #pragma unroll
            for (int ii = 0; ii < 4; ii++) {
                int r = warpM * 64 + ii * 16 + groupID;
                afr[ii][0] = as[r * GSTRIDE + kg * 8 + tid4];
                afr[ii][1] = as[(r + 8) * GSTRIDE + kg * 8 + tid4];
                afr[ii][2] = as[r * GSTRIDE + kg * 8 + tid4 + 4];
                afr[ii][3] = as[(r + 8) * GSTRIDE + kg * 8 + tid4 + 4];
            }
            #pragma unroll
            for (int j = 0; j < 4; j++) {
                int cn = warpN * 32 + j * 8 + groupID;
                bfr[j][0] = bs[cn * GSTRIDE + kg * 8 + tid4];
                bfr[j][1] = bs[cn * GSTRIDE + kg * 8 + tid4 + 4];
            }
            #pragma unroll
            for (int ii = 0; ii < 4; ii++)
                #pragma unroll
                for (int j = 0; j < 4; j++)
                    mma16(acc[ii][j], afr[ii], bfr[j]);
        }
    }

    // epilogue
    float*  Cf = (float*)Cv;
    __half* Ch = (__half*)Cv;
    #pragma unroll
    for (int i = 0; i < 4; i++) {
        int r0 = mBase + warpM * 64 + i * 16 + groupID;
        int r1 = r0 + 8;
        #pragma unroll
        for (int j = 0; j < 4; j++) {
            int cn = nBase + warpN * 32 + j * 8 + tid4 * 2;
            float bv0, bv1;
            if (EPI == 1) {
                bv0 = (cn < 768) ? bias[cn] : ((cn < 1536) ? 0.f : bias2[cn - 1536]);
                int c1 = cn + 1;
                bv1 = (c1 < 768) ? bias[c1] : ((c1 < 1536) ? 0.f : bias2[c1 - 1536]);
            } else {
                bv0 = bias[cn]; bv1 = bias[cn + 1];
            }
            #pragma unroll
            for (int rr = 0; rr < 2; rr++) {
                int gm = rr ? r1 : r0;
                if (gm >= M) continue;
                size_t off = (size_t)gm * Nn + cn;
                float v0 = acc[i][j][rr * 2 + 0] + bv0;
                float v1 = acc[i][j][rr * 2 + 1] + bv1;
                if (EPI == 1) {
                    *(__half2*)&Ch[off] = __floats2half2_rn(v0, v1);
                } else if (EPI == 2) {
                    v0 = 0.5f * v0 * (1.f + erff(v0 * 0.70710678118654752f));
                    v1 = 0.5f * v1 * (1.f + erff(v1 * 0.70710678118654752f));
                    *(__half2*)&Ch[off] = __floats2half2_rn(v0, v1);
                } else {
                    v0 += res[off]; v1 += res[off + 1];
                    float2 o; o.x = v0; o.y = v1;
                    *(float2*)&Cf[off] = o;
                }
            }
        }
    }
}

// ---------------- fp16 flash attention: 128 q/block, P stays in registers ----------------
#define QSTR 72   /* halves */
#define KSTR 72
#define VSTR 72
#define NCH  10
#define ATTN_SMEM ((128*QSTR + 4*64*KSTR) * 2)   /* 55296 B */

__global__ void __launch_bounds__(256, 2)
attn_kernel(const __half* __restrict__ qkv, const float* __restrict__ rpbf,
            __half* __restrict__ out)
{
    extern __shared__ __half smh[];
    __half* sQ  = smh;
    __half* sK0 = smh + 128 * QSTR;
    __half* sV0 = sK0 + 64 * KSTR;
    __half* sK1 = sV0 + 64 * VSTR;
    __half* sV1 = sK1 + 64 * KSTR;

    const int tid = threadIdx.x;
    const int warp = tid >> 5, lane = tid & 31;
    const int groupID = lane >> 2, tid4 = lane & 3;
    const int q0 = blockIdx.x * 128;
    const int h  = blockIdx.y;
    const int b  = blockIdx.z;
    const size_t qkv_base = (size_t)b * N_ * QKVD + h * 64;

    // Q tile: 128 rows x 64 halves (8 x 16B per row)
    {
        const __half* qsrc = qkv + qkv_base;
        #pragma unroll
        for (int p = 0; p < 4; p++) {
            int u = p * 256 + tid;          // 0..1023
            int row = u >> 3;
            int cc = (u & 7) * 8;           // half offset
            int n = q0 + row;
            bool v = n < N_;
            cp16(&sQ[row * QSTR + cc], v ? (qsrc + (size_t)n * QKVD + cc) : qkv, v);
        }
        cp_commit();
    }

    auto issueKV = [&](int c) {
        __half* kD = (c & 1) ? sK1 : sK0;
        __half* vD = (c & 1) ? sV1 : sV0;
        const __half* ks = qkv + qkv_base + 768;
        const __half* vs = qkv + qkv_base + 1536;
        #pragma unroll
        for (int p = 0; p < 2; p++) {
            int u = p * 256 + tid;          // 0..511
            int row = u >> 3;
            int cc = (u & 7) * 8;
            int kk = c * 64 + row;
            bool v = kk < N_;
            cp16(&kD[row * KSTR + cc], v ? (ks + (size_t)kk * QKVD + cc) : qkv, v);
            cp16(&vD[row * VSTR + cc], v ? (vs + (size_t)kk * QKVD + cc) : qkv, v);
        }
        cp_commit();
    };

    issueKV(0);
    issueKV(1);

    // wait for Q, read A-fragments (validated GEMM layout)
    cp_wait<2>();
    __syncthreads();
    unsigned aq[4][4];
    {
        const unsigned* qrow  = (const unsigned*)(sQ + (warp * 16 + groupID) * QSTR);
        const unsigned* qrow8 = (const unsigned*)(sQ + (warp * 16 + groupID + 8) * QSTR);
        #pragma unroll
        for (int ks = 0; ks < 4; ks++) {
            aq[ks][0] = qrow [ks * 8 + tid4];
            aq[ks][1] = qrow8[ks * 8 + tid4];
            aq[ks][2] = qrow [ks * 8 + tid4 + 4];
            aq[ks][3] = qrow8[ks * 8 + tid4 + 4];
        }
    }

    const int n0 = q0 + warp * 16 + groupID;
    const int n1 = n0 + 8;
    const float* rpb0 = rpbf + ((size_t)h * N_ + (n0 < N_ ? n0 : 0)) * N_;
    const float* rpb1 = rpbf + ((size_t)h * N_ + (n1 < N_ ? n1 : 0)) * N_;

    float m0 = -1e30f, m1 = -1e30f, l0 = 0.f, l1 = 0.f;
    float oacc[8][4];
    #pragma unroll
    for (int j = 0; j < 8; j++)
        #pragma unroll
        for (int r = 0; r < 4; r++) oacc[j][r] = 0.f;

    // ldmatrix per-lane source row/col (within a 16x16 V sub-tile)
    const int lmrow = (lane & 7) + ((lane >> 3) & 1) * 8;
    const int lmcol = (lane >> 4) * 8;

    for (int c = 0; c < NCH; c++) {
        cp_wait<1>();
        __syncthreads();
        const __half* sK = (c & 1) ? sK1 : sK0;
        const __half* sV = (c & 1) ? sV1 : sV0;

        // ---- S = Q K^T (fp32 accum) ----
        float sc[8][4];
        #pragma unroll
        for (int j = 0; j < 8; j++)
            #pragma unroll
            for (int r = 0; r < 4; r++) sc[j][r] = 0.f;
        #pragma unroll
        for (int j = 0; j < 8; j++) {
            const unsigned* krow = (const unsigned*)(sK + (j * 8 + groupID) * KSTR);
            #pragma unroll
            for (int ks = 0; ks < 4; ks++) {
                unsigned bk[2];
                bk[0] = krow[ks * 8 + tid4];
                bk[1] = krow[ks * 8 + tid4 + 4];
                mma16(sc[j], aq[ks], bk);
            }
        }

        // ---- scale + rpb + mask; online softmax ----
        const int cbase = c * 64;
        float mx0 = m0, mx1 = m1;
        #pragma unroll
        for (int j = 0; j < 8; j++) {
            int col = cbase + j * 8 + tid4 * 2;
            bool v0 = col < N_, v1 = (col + 1) < N_;
            sc[j][0] = v0 ? sc[j][0] * SCALE_ + rpb0[col]     : -1e30f;
            sc[j][1] = v1 ? sc[j][1] * SCALE_ + rpb0[col + 1] : -1e30f;
            sc[j][2] = v0 ? sc[j][2] * SCALE_ + rpb1[col]     : -1e30f;
            sc[j][3] = v1 ? sc[j][3] * SCALE_ + rpb1[col + 1] : -1e30f;
            mx0 = fmaxf(mx0, fmaxf(sc[j][0], sc[j][1]));
            mx1 = fmaxf(mx1, fmaxf(sc[j][2], sc[j][3]));
        }
        #pragma unroll
        for (int o = 1; o <= 2; o <<= 1) {
            mx0 = fmaxf(mx0, __shfl_xor_sync(0xffffffffu, mx0, o));
            mx1 = fmaxf(mx1, __shfl_xor_sync(0xffffffffu, mx1, o));
        }
        float f0 = __expf(m0 - mx0), f1 = __expf(m1 - mx1);
        m0 = mx0; m1 = mx1;

        float rs0 = 0.f, rs1 = 0.f;
        #pragma unroll
        for (int j = 0; j < 8; j++) {
            sc[j][0] = __expf(sc[j][0] - m0);
            sc[j][1] = __expf(sc[j][1] - m0);
            sc[j][2] = __expf(sc[j][2] - m1);
            sc[j][3] = __expf(sc[j][3] - m1);
            rs0 += sc[j][0] + sc[j][1];
            rs1 += sc[j][2] + sc[j][3];
        }
        #pragma unroll
        for (int o = 1; o <= 2; o <<= 1) {
            rs0 += __shfl_xor_sync(0xffffffffu, rs0, o);
            rs1 += __shfl_xor_sync(0xffffffffu, rs1, o);
        }
        l0 = l0 * f0 + rs0;
        l1 = l1 * f1 + rs1;
        #pragma unroll
        for (int j = 0; j < 8; j++) {
            oacc[j][0] *= f0; oacc[j][1] *= f0;
            oacc[j][2] *= f1; oacc[j][3] *= f1;
        }

        // ---- P fragments from registers (C-layout == A-layout) ----
        unsigned ap[4][4];
        #pragma unroll
        for (int ks = 0; ks < 4; ks++) {
            ap[ks][0] = packh2(sc[2*ks][0],   sc[2*ks][1]);
            ap[ks][1] = packh2(sc[2*ks][2],   sc[2*ks][3]);
            ap[ks][2] = packh2(sc[2*ks+1][0], sc[2*ks+1][1]);
            ap[ks][3] = packh2(sc[2*ks+1][2], sc[2*ks+1][3]);
        }

        // ---- O += P V  (V B-fragments via ldmatrix.trans) ----
        #pragma unroll
        for (int ks = 0; ks < 4; ks++) {
            #pragma unroll
            for (int n16 = 0; n16 < 4; n16++) {
                unsigned bv[4];
                ldmat4t(bv, sV + (ks * 16 + lmrow) * VSTR + n16 * 16 + lmcol);
                mma16(oacc[2*n16],     ap[ks], bv);
                mma16(oacc[2*n16 + 1], ap[ks], bv + 2);
            }
        }

        __syncthreads();
        if (c + 2 < NCH) issueKV(c + 2);
        else cp_commit();
    }

    // ---- normalize + store ----
    {
        float inv0 = 1.f / l0, inv1 = 1.f / l1;
        #pragma unroll
        for (int j = 0; j < 8; j++) {
            int col = j * 8 + tid4 * 2;
            if (n0 < N_) {
                *(__half2*)&out[((size_t)b * N_ + n0) * DIM_ + h * 64 + col] =
                    __floats2half2_rn(oacc[j][0] * inv0, oacc[j][1] * inv0);
            }
            if (n1 < N_) {
                *(__half2*)&out[((size_t)b * N_ + n1) * DIM_ + h * 64 + col] =
                    __floats2half2_rn(oacc[j][2] * inv1, oacc[j][3] * inv1);
            }
        }
    }
}

// ---------------- launch ----------------
extern "C" void kernel_launch(void* const* d_in, const int* in_sizes, int n_in,
                              void* d_out, int out_size)
{
    const float* x     = (const float*)d_in[0];
    const float* n1g   = (const float*)d_in[1];
    const float* n1b   = (const float*)d_in[2];
    const float* qkvw  = (const float*)d_in[3];
    const float* qb    = (const float*)d_in[4];
    const float* vb    = (const float*)d_in[5];
    const float* rpbt  = (const float*)d_in[6];
    const float* projw = (const float*)d_in[7];
    const float* projb = (const float*)d_in[8];
    const float* n2g   = (const float*)d_in[9];
    const float* n2b   = (const float*)d_in[10];
    const float* fc1w  = (const float*)d_in[11];
    const float* fc1b  = (const float*)d_in[12];
    const float* fc2w  = (const float*)d_in[13];
    const float* fc2b  = (const float*)d_in[14];
    const int*   ridx  = (const int*)d_in[15];
    float* out = (float*)d_out;

    __half *ph, *pqkv, *patt, *pm, *pwqkv, *pwproj, *pwfc1, *pwfc2;
    float *prpb;
    cudaGetSymbolAddress((void**)&ph,    g_h);
    cudaGetSymbolAddress((void**)&pqkv,  g_qkv);
    cudaGetSymbolAddress((void**)&patt,  g_att);
    cudaGetSymbolAddress((void**)&pm,    g_m);
    cudaGetSymbolAddress((void**)&prpb,  g_rpbf);
    cudaGetSymbolAddress((void**)&pwqkv, g_wqkv);
    cudaGetSymbolAddress((void**)&pwproj,g_wproj);
    cudaGetSymbolAddress((void**)&pwfc1, g_wfc1);
    cudaGetSymbolAddress((void**)&pwfc2, g_wfc2);

    static bool attr_done = false;
    if (!attr_done) {
        cudaFuncSetAttribute(gemm_h<1>, cudaFuncAttributeMaxDynamicSharedMemorySize, GEMM_SMEM);
        cudaFuncSetAttribute(gemm_h<2>, cudaFuncAttributeMaxDynamicSharedMemorySize, GEMM_SMEM);
        cudaFuncSetAttribute(gemm_h<3>, cudaFuncAttributeMaxDynamicSharedMemorySize, GEMM_SMEM);
        cudaFuncSetAttribute(attn_kernel, cudaFuncAttributeMaxDynamicSharedMemorySize, ATTN_SMEM);
        attr_done = true;
    }

    // weight conversions (fp32 -> fp16)
    f2h_kernel<<<(QKVD * DIM_ / 4 + 255) / 256, 256>>>(qkvw,  pwqkv,  QKVD * DIM_ / 4);
    f2h_kernel<<<(DIM_ * DIM_ / 4 + 255) / 256, 256>>>(projw, pwproj, DIM_ * DIM_ / 4);
    f2h_kernel<<<(MLP_ * DIM_ / 4 + 255) / 256, 256>>>(fc1w,  pwfc1,  MLP_ * DIM_ / 4);
    f2h_kernel<<<(DIM_ * MLP_ / 4 + 255) / 256, 256>>>(fc2w,  pwfc2,  DIM_ * MLP_ / 4);

    const int mTiles = (MTOK + 127) / 128;

    ln_kernel<<<MTOK, 256>>>(x, n1g, n1b, ph);
    rpb_expand<<<(NH_ * N_ * N_ + 255) / 256, 256>>>(rpbt, ridx, prpb);
    gemm_h<1><<<dim3(QKVD / 128, mTiles), 256, GEMM_SMEM>>>(ph, pwqkv, pqkv, MTOK, QKVD, DIM_, qb, vb, nullptr);
    attn_kernel<<<dim3((N_ + 127) / 128, NH_, B_), 256, ATTN_SMEM>>>(pqkv, prpb, patt);
    gemm_h<3><<<dim3(DIM_ / 128, mTiles), 256, GEMM_SMEM>>>(patt, pwproj, out, MTOK, DIM_, DIM_, projb, nullptr, x);
    ln_kernel<<<MTOK, 256>>>(out, n2g, n2b, ph);
    gemm_h<2><<<dim3(MLP_ / 128, mTiles), 256, GEMM_SMEM>>>(ph, pwfc1, pm, MTOK, MLP_, DIM_, fc1b, nullptr, nullptr);
    gemm_h<3><<<dim3(DIM_ / 128, mTiles), 256, GEMM_SMEM>>>(pm, pwfc2, out, MTOK, DIM_, MLP_, fc2b, nullptr, out);
}